// round 2
// baseline (speedup 1.0000x reference)
#include <cuda_runtime.h>
#include <math.h>

// ---------------- problem constants ----------------
#define Cc   128      // channels (d_model)
#define Hd   128
#define Wd   128
#define HWs  16384    // H*W
#define BT   16       // b*t images
#define NB   2        // batch b
#define TT   8        // frames per clip

// ---------------- device scratch (no cudaMalloc allowed) ----------------
__device__ float g_q [(size_t)BT * Cc * HWs];
__device__ float g_k [(size_t)BT * Cc * HWs];
__device__ float g_v [(size_t)BT * Cc * HWs];
__device__ float g_ao[(size_t)BT * Cc * HWs];
__device__ float g_part[(size_t)1 << 22];     // partial scores (max 4M floats)
__device__ float g_attn[(size_t)NB * 512 * 512];

// ---------------- window gather addressing ----------------
// token = ((t*oh + oy)*ow + ox), feature e = ((c*ph + py)*pw + px), square windows.
__device__ __forceinline__ size_t win_addr(int b, int cslice, int token, int e,
                                           int lph, int loh)
{
    int pm = (1 << lph) - 1;
    int om = (1 << loh) - 1;
    int px = e & pm;
    int py = (e >> lph) & pm;
    int c  = e >> (2 * lph);
    int ox = token & om;
    int oy = (token >> loh) & om;
    int t  = token >> (2 * loh);
    int img = b * TT + t;
    int yy = (oy << lph) + py;
    int xx = (ox << lph) + px;
    return ((size_t)(img * Cc + cslice + c)) * HWs + (size_t)yy * Wd + xx;
}

// ---------------- kernel 1: fused conv1x1 (one of q/k/v per launch) ----------------
__global__ __launch_bounds__(256)
void conv1x1_kernel(const float* __restrict__ x,
                    const float* __restrict__ w,
                    const float* __restrict__ bias,
                    int which)
{
    __shared__ float Xs[16][128];
    __shared__ float Ws[16][128];
    float* out = (which == 0) ? g_q : (which == 1) ? g_k : g_v;

    int n  = blockIdx.y;
    int p0 = blockIdx.x * 128;
    int tx = threadIdx.x, ty = threadIdx.y;
    int tid = ty * 16 + tx;

    float acc[8][8];
#pragma unroll
    for (int i = 0; i < 8; i++)
#pragma unroll
        for (int j = 0; j < 8; j++) acc[i][j] = 0.f;

    const float* xb = x + (size_t)n * Cc * HWs;

    for (int k0 = 0; k0 < Cc; k0 += 16) {
        {
            int kk = tid >> 7;        // 0..1
            int pp = tid & 127;
#pragma unroll
            for (int r = 0; r < 8; r++)
                Xs[kk + 2 * r][pp] = xb[(size_t)(k0 + kk + 2 * r) * HWs + p0 + pp];
        }
        {
            int kk = tid & 15;
            int oc = tid >> 4;        // 0..15
#pragma unroll
            for (int r = 0; r < 8; r++)
                Ws[kk][oc + 16 * r] = w[(size_t)(oc + 16 * r) * Cc + k0 + kk];
        }
        __syncthreads();
#pragma unroll
        for (int kk = 0; kk < 16; kk++) {
            float xr[8], wr[8];
#pragma unroll
            for (int j = 0; j < 8; j++) xr[j] = Xs[kk][tx + 16 * j];
#pragma unroll
            for (int i = 0; i < 8; i++) wr[i] = Ws[kk][ty + 16 * i];
#pragma unroll
            for (int i = 0; i < 8; i++)
#pragma unroll
                for (int j = 0; j < 8; j++) acc[i][j] += wr[i] * xr[j];
        }
        __syncthreads();
    }

#pragma unroll
    for (int i = 0; i < 8; i++) {
        int oc = ty + 16 * i;
        float bv = bias[oc];
#pragma unroll
        for (int j = 0; j < 8; j++)
            out[((size_t)n * Cc + oc) * HWs + p0 + tx + 16 * j] = acc[i][j] + bv;
    }
}

// ---------------- kernel 2: windowed scores (partial over d-splits) ----------------
template<int BN, int BM, int TN, int TM>
__global__ __launch_bounds__(256)
void scores_kernel(int n, int cslice, int lph, int loh,
                   int tilesM, int dchunk)
{
    __shared__ float Qs[BN][33];
    __shared__ float Ks[BM][33];

    int b  = blockIdx.y;
    int z  = blockIdx.z;
    int tn = blockIdx.x / tilesM;
    int tm = blockIdx.x - tn * tilesM;
    int n0 = tn * BN, m0 = tm * BM;
    int tx = threadIdx.x, ty = threadIdx.y;
    int tid = ty * 16 + tx;

    float acc[TN][TM];
#pragma unroll
    for (int i = 0; i < TN; i++)
#pragma unroll
        for (int j = 0; j < TM; j++) acc[i][j] = 0.f;

    int r0 = ty * TN, c0 = tx * TM;
    bool active = (r0 < BN) && (c0 < BM);

    int kstart = z * dchunk;
    int kend   = kstart + dchunk;

    for (int k0 = kstart; k0 < kend; k0 += 32) {
        for (int idx = tid; idx < BN * 32; idx += 256) {
            int r = idx >> 5, cc = idx & 31;
            Qs[r][cc] = g_q[win_addr(b, cslice, n0 + r, k0 + cc, lph, loh)];
        }
        for (int idx = tid; idx < BM * 32; idx += 256) {
            int r = idx >> 5, cc = idx & 31;
            Ks[r][cc] = g_k[win_addr(b, cslice, m0 + r, k0 + cc, lph, loh)];
        }
        __syncthreads();
        if (active) {
#pragma unroll
            for (int kk = 0; kk < 32; kk++) {
                float qr[TN], kr[TM];
#pragma unroll
                for (int i = 0; i < TN; i++) qr[i] = Qs[r0 + i][kk];
#pragma unroll
                for (int j = 0; j < TM; j++) kr[j] = Ks[c0 + j][kk];
#pragma unroll
                for (int i = 0; i < TN; i++)
#pragma unroll
                    for (int j = 0; j < TM; j++) acc[i][j] += qr[i] * kr[j];
            }
        }
        __syncthreads();
    }

    if (active) {
        size_t base = ((size_t)(z * NB + b)) * n * n;
#pragma unroll
        for (int i = 0; i < TN; i++)
#pragma unroll
            for (int j = 0; j < TM; j++)
                g_part[base + (size_t)(n0 + r0 + i) * n + (m0 + c0 + j)] = acc[i][j];
    }
}

// ---------------- kernel 3: reduce partials + softmax ----------------
__global__ __launch_bounds__(256)
void softmax_kernel(int n, int nsplit, float inv_sqrt_d)
{
    __shared__ float sbuf[512];
    __shared__ float red[256];
    int row = blockIdx.x;
    int b   = blockIdx.y;
    int tid = threadIdx.x;

    for (int m = tid; m < n; m += 256) {
        float s = 0.f;
        for (int z = 0; z < nsplit; z++)
            s += g_part[((size_t)(z * NB + b) * n + row) * n + m];
        sbuf[m] = s * inv_sqrt_d;
    }
    __syncthreads();

    float lm = -1e30f;
    for (int m = tid; m < n; m += 256) lm = fmaxf(lm, sbuf[m]);
    red[tid] = lm;
    __syncthreads();
    for (int s = 128; s > 0; s >>= 1) {
        if (tid < s) red[tid] = fmaxf(red[tid], red[tid + s]);
        __syncthreads();
    }
    float mx = red[0];
    __syncthreads();

    float ls = 0.f;
    for (int m = tid; m < n; m += 256) {
        float e = expf(sbuf[m] - mx);
        sbuf[m] = e;
        ls += e;
    }
    red[tid] = ls;
    __syncthreads();
    for (int s = 128; s > 0; s >>= 1) {
        if (tid < s) red[tid] += red[tid + s];
        __syncthreads();
    }
    float inv = 1.0f / red[0];

    for (int m = tid; m < n; m += 256)
        g_attn[((size_t)b * n + row) * n + m] = sbuf[m] * inv;
}

// ---------------- kernel 4: AV (attn @ V, scattered back to image layout) ----------------
template<int BN, int TN>
__global__ __launch_bounds__(256)
void av_kernel(int n, int cslice, int lph, int loh)
{
    __shared__ float As[BN][33];
    __shared__ float Vs[32][64];

    int b  = blockIdx.z;
    int n0 = blockIdx.y * BN;
    int e0 = blockIdx.x * 64;
    int tx = threadIdx.x, ty = threadIdx.y;
    int tid = ty * 16 + tx;

    float acc[TN][4];
#pragma unroll
    for (int i = 0; i < TN; i++)
#pragma unroll
        for (int j = 0; j < 4; j++) acc[i][j] = 0.f;

    int r0 = ty * TN;
    bool active = (r0 < BN);

    for (int m0 = 0; m0 < n; m0 += 32) {
        for (int idx = tid; idx < BN * 32; idx += 256) {
            int r = idx >> 5, cc = idx & 31;
            As[r][cc] = (m0 + cc < n)
                ? g_attn[((size_t)b * n + n0 + r) * n + m0 + cc] : 0.f;
        }
        for (int idx = tid; idx < 32 * 64; idx += 256) {
            int mm = idx >> 6, ee = idx & 63;
            Vs[mm][ee] = (m0 + mm < n)
                ? g_v[win_addr(b, cslice, m0 + mm, e0 + ee, lph, loh)] : 0.f;
        }
        __syncthreads();
        if (active) {
#pragma unroll
            for (int kk = 0; kk < 32; kk++) {
                float vr[4];
#pragma unroll
                for (int j = 0; j < 4; j++) vr[j] = Vs[kk][tx * 4 + j];
#pragma unroll
                for (int i = 0; i < TN; i++) {
                    float a = As[r0 + i][kk];
#pragma unroll
                    for (int j = 0; j < 4; j++) acc[i][j] += a * vr[j];
                }
            }
        }
        __syncthreads();
    }

    if (active) {
#pragma unroll
        for (int i = 0; i < TN; i++)
#pragma unroll
            for (int j = 0; j < 4; j++)
                g_ao[win_addr(b, cslice, n0 + r0 + i, e0 + tx * 4 + j, lph, loh)] = acc[i][j];
    }
}

// ---------------- kernel 5: conv3x3 SAME + bias + relu ----------------
__global__ __launch_bounds__(256)
void conv3x3_kernel(const float* __restrict__ w,
                    const float* __restrict__ bias,
                    float* __restrict__ out)
{
    __shared__ float xr[3][130];
    __shared__ float ws[9][128];

    int n = blockIdx.y;
    int y = blockIdx.x;
    int tx = threadIdx.x, ty = threadIdx.y;
    int tid = ty * 16 + tx;

    float acc[8][8];
#pragma unroll
    for (int i = 0; i < 8; i++)
#pragma unroll
        for (int j = 0; j < 8; j++) acc[i][j] = 0.f;

    const float* in = g_ao + (size_t)n * Cc * HWs;

    for (int c = 0; c < Cc; c++) {
        for (int i = tid; i < 3 * 130; i += 256) {
            int ry = i / 130, rx = i - ry * 130;
            int yy = y + ry - 1, xx = rx - 1;
            float v = 0.f;
            if (yy >= 0 && yy < Hd && xx >= 0 && xx < Wd)
                v = in[(size_t)c * HWs + (size_t)yy * Wd + xx];
            xr[ry][rx] = v;
        }
        for (int i = tid; i < 1152; i += 256) {
            int oc = i / 9, tap = i - oc * 9;
            ws[tap][oc] = w[((size_t)oc * Cc + c) * 9 + tap];
        }
        __syncthreads();

#pragma unroll
        for (int ky = 0; ky < 3; ky++) {
#pragma unroll
            for (int kx = 0; kx < 3; kx++) {
                float wr[8];
#pragma unroll
                for (int i = 0; i < 8; i++) wr[i] = ws[ky * 3 + kx][ty + 16 * i];
#pragma unroll
                for (int j = 0; j < 8; j++) {
                    float xv = xr[ky][tx + 16 * j + kx];
#pragma unroll
                    for (int i = 0; i < 8; i++) acc[i][j] += wr[i] * xv;
                }
            }
        }
        __syncthreads();
    }

#pragma unroll
    for (int i = 0; i < 8; i++) {
        int oc = ty + 16 * i;
        float bv = bias[oc];
#pragma unroll
        for (int j = 0; j < 8; j++) {
            float v = acc[i][j] + bv;
            out[((size_t)(n * Cc + oc)) * HWs + (size_t)y * Wd + tx + 16 * j] =
                fmaxf(v, 0.f);
        }
    }
}

// ---------------- launch ----------------
extern "C" void kernel_launch(void* const* d_in, const int* in_sizes, int n_in,
                              void* d_out, int out_size)
{
    const float* x  = (const float*)d_in[0];
    const float* wq = (const float*)d_in[1];
    const float* bq = (const float*)d_in[2];
    const float* wk = (const float*)d_in[3];
    const float* bk = (const float*)d_in[4];
    const float* wv = (const float*)d_in[5];
    const float* bv = (const float*)d_in[6];
    const float* wo = (const float*)d_in[7];
    const float* bo = (const float*)d_in[8];
    float* out = (float*)d_out;

    dim3 blk(16, 16);

    // QKV 1x1 convs
    conv1x1_kernel<<<dim3(HWs / 128, BT), blk>>>(x, wq, bq, 0);
    conv1x1_kernel<<<dim3(HWs / 128, BT), blk>>>(x, wk, bk, 1);
    conv1x1_kernel<<<dim3(HWs / 128, BT), blk>>>(x, wv, bv, 2);

    // per-scale windowed attention
    // scale 0: ph=128, oh=1, n=8,  d=524288
    {
        const int n = 8, d = 524288, cs = 0, lph = 7, loh = 0, S = 1024;
        float isd = (float)(1.0 / sqrt((double)d));
        scores_kernel<8, 8, 1, 1><<<dim3(1, NB, S), blk>>>(n, cs, lph, loh, 1, d / S);
        softmax_kernel<<<dim3(n, NB), 256>>>(n, S, isd);
        av_kernel<8, 1><<<dim3(d / 64, 1, NB), blk>>>(n, cs, lph, loh);
    }
    // scale 1: ph=64, oh=2, n=32, d=131072
    {
        const int n = 32, d = 131072, cs = 32, lph = 6, loh = 1, S = 512;
        float isd = (float)(1.0 / sqrt((double)d));
        scores_kernel<32, 32, 2, 2><<<dim3(1, NB, S), blk>>>(n, cs, lph, loh, 1, d / S);
        softmax_kernel<<<dim3(n, NB), 256>>>(n, S, isd);
        av_kernel<32, 2><<<dim3(d / 64, 1, NB), blk>>>(n, cs, lph, loh);
    }
    // scale 2: ph=32, oh=4, n=128, d=32768
    {
        const int n = 128, d = 32768, cs = 64, lph = 5, loh = 2, S = 32;
        float isd = (float)(1.0 / sqrt((double)d));
        scores_kernel<32, 32, 2, 2><<<dim3(16, NB, S), blk>>>(n, cs, lph, loh, 4, d / S);
        softmax_kernel<<<dim3(n, NB), 256>>>(n, S, isd);
        av_kernel<32, 2><<<dim3(d / 64, 4, NB), blk>>>(n, cs, lph, loh);
    }
    // scale 3: ph=16, oh=8, n=512, d=8192
    {
        const int n = 512, d = 8192, cs = 96, lph = 4, loh = 3, S = 8;
        float isd = (float)(1.0 / sqrt((double)d));
        scores_kernel<64, 64, 4, 4><<<dim3(64, NB, S), blk>>>(n, cs, lph, loh, 8, d / S);
        softmax_kernel<<<dim3(n, NB), 256>>>(n, S, isd);
        av_kernel<64, 4><<<dim3(d / 64, 8, NB), blk>>>(n, cs, lph, loh);
    }

    // output 3x3 conv + bias + relu
    conv3x3_kernel<<<dim3(Hd, BT), blk>>>(wo, bo, out);

    (void)in_sizes; (void)n_in; (void)out_size;
}

// round 3
// speedup vs baseline: 1.0282x; 1.0282x over previous
#include <cuda_runtime.h>
#include <math.h>

typedef unsigned long long ull;

#define Cc 128
#define Hd 128
#define Wd 128
#define HWs 16384
#define BT 16
#define NBm 2

// ---------------- device scratch ----------------
__device__ float  g_qw[(size_t)4 * 8388608];
__device__ float  g_kw[(size_t)4 * 8388608];
__device__ float  g_vw[(size_t)4 * 8388608];
__device__ float  g_ow[(size_t)4 * 8388608];
__device__ float2 g_ao2[(size_t)BT * 64 * HWs];
__device__ float  g_part[(size_t)1 << 24];
__device__ float  g_attn[(size_t)NBm * 512 * 512];
__device__ float2 g_wt2[64 * 9 * 128];

__device__ __forceinline__ void ffma2(ull& d, ull a, ull b) {
    asm("fma.rn.f32x2 %0, %1, %2, %0;" : "+l"(d) : "l"(a), "l"(b));
}
__device__ __forceinline__ float hsum2(ull v) {
    float2 f = *reinterpret_cast<float2*>(&v);
    return f.x + f.y;
}
__device__ __forceinline__ ull pack2(float a) {
    ull r; asm("mov.b64 %0,{%1,%1};" : "=l"(r) : "f"(a)); return r;
}

// ============ conv1x1 -> windowed q/k/v ============
__global__ __launch_bounds__(256)
void conv1x1w_kernel(const float* __restrict__ x, const float* __restrict__ w,
                     const float* __restrict__ bias, int which)
{
    __shared__ float Xs[128][18];
    __shared__ float Ws[128][18];
    float* out = (which == 0) ? g_qw : (which == 1) ? g_kw : g_vw;

    int img = blockIdx.y, y = blockIdx.x;
    int tx = threadIdx.x, ty = threadIdx.y, tid = ty * 16 + tx;

    ull acc[8][8];
#pragma unroll
    for (int i = 0; i < 8; i++)
#pragma unroll
        for (int j = 0; j < 8; j++) acc[i][j] = 0ull;

    const float* xb = x + ((size_t)img * Cc) * HWs + (size_t)y * Wd;

    for (int k0 = 0; k0 < Cc; k0 += 16) {
        for (int idx = tid; idx < 512; idx += 256) {
            int kk = idx >> 5, p4 = (idx & 31) * 4;
            float4 v = *(const float4*)(xb + (size_t)(k0 + kk) * HWs + p4);
            Xs[p4][kk] = v.x; Xs[p4 + 1][kk] = v.y;
            Xs[p4 + 2][kk] = v.z; Xs[p4 + 3][kk] = v.w;
        }
        for (int idx = tid; idx < 512; idx += 256) {
            int oc = idx >> 2, k4 = (idx & 3) * 4;
            float4 v = *(const float4*)(w + (size_t)oc * Cc + k0 + k4);
            Ws[oc][k4] = v.x; Ws[oc][k4 + 1] = v.y;
            Ws[oc][k4 + 2] = v.z; Ws[oc][k4 + 3] = v.w;
        }
        __syncthreads();
#pragma unroll
        for (int kk2 = 0; kk2 < 8; kk2++) {
            ull w2[8], x2[8];
#pragma unroll
            for (int i = 0; i < 8; i++) w2[i] = *(const ull*)&Ws[ty * 8 + i][2 * kk2];
#pragma unroll
            for (int j = 0; j < 8; j++) x2[j] = *(const ull*)&Xs[tx + 16 * j][2 * kk2];
#pragma unroll
            for (int i = 0; i < 8; i++)
#pragma unroll
                for (int j = 0; j < 8; j++) ffma2(acc[i][j], w2[i], x2[j]);
        }
        __syncthreads();
    }

    int b = img >> 3, t = img & 7;
#pragma unroll
    for (int i = 0; i < 8; i++) {
        int oc = ty * 8 + i;
        int s = oc >> 5, lph = 7 - s;
        int n_s = 8 << (2 * s), d_s = 524288 >> (2 * s);
        int phm = (1 << lph) - 1;
        int oy = y >> lph, py = y & phm;
        int tokb = (((t << s) + oy) << s);
        int eb = ((((oc & 31) << lph) + py) << lph);
        float bv = bias[oc];
        size_t rowb = (size_t)s * 8388608 + ((size_t)(b * n_s)) * d_s + eb;
#pragma unroll
        for (int j = 0; j < 8; j++) {
            int xx = tx + 16 * j;
            out[rowb + (size_t)(tokb + (xx >> lph)) * d_s + (xx & phm)] =
                hsum2(acc[i][j]) + bv;
        }
    }
}

// ============ scale-0 scores (n=8, d=524288) ============
__global__ __launch_bounds__(256)
void scores0_kernel()
{
    __shared__ float Qs[8][516];
    __shared__ float Ks[8][516];
    __shared__ float sred[256];
    int z = blockIdx.x, b = blockIdx.y, tid = threadIdx.x;
    const int d = 524288;

    const float* qb = g_qw + ((size_t)(b * 8)) * d + z * 512;
    const float* kb = g_kw + ((size_t)(b * 8)) * d + z * 512;
    for (int idx = tid; idx < 1024; idx += 256) {
        int r = idx >> 7, c4 = (idx & 127) * 4;
        *(float4*)&Qs[r][c4] = *(const float4*)(qb + (size_t)r * d + c4);
        *(float4*)&Ks[r][c4] = *(const float4*)(kb + (size_t)r * d + c4);
    }
    __syncthreads();

    int rm = tid & 63, r = rm >> 3, m = rm & 7, kg = tid >> 6;
    ull acc = 0ull;
    int kb0 = kg * 128;
#pragma unroll
    for (int kk2 = 0; kk2 < 64; kk2++)
        ffma2(acc, *(const ull*)&Qs[r][kb0 + 2 * kk2], *(const ull*)&Ks[m][kb0 + 2 * kk2]);
    sred[tid] = hsum2(acc);
    __syncthreads();
    if (tid < 64)
        g_part[(size_t)(z * NBm + b) * 64 + tid] =
            sred[tid] + sred[tid + 64] + sred[tid + 128] + sred[tid + 192];
}

// ============ dense scores (scales 1-3), split-k ============
template<int BN, int TN>
__global__ __launch_bounds__(256)
void scores2_kernel(int n, int d, long long off_ll, int tilesM, int dchunk)
{
    __shared__ float Qs[BN][68];
    __shared__ float Ks[BN][68];
    size_t off = (size_t)off_ll;
    int b = blockIdx.y, z = blockIdx.z;
    int tn = blockIdx.x / tilesM, tm = blockIdx.x - tn * tilesM;
    int n0 = tn * BN, m0 = tm * BN;
    int tx = threadIdx.x, ty = threadIdx.y, tid = ty * 16 + tx;

    ull acc[TN][TN];
#pragma unroll
    for (int i = 0; i < TN; i++)
#pragma unroll
        for (int j = 0; j < TN; j++) acc[i][j] = 0ull;

    const float* qb = g_qw + off + ((size_t)(b * n + n0)) * d;
    const float* kb = g_kw + off + ((size_t)(b * n + m0)) * d;
    int r0 = ty * TN;
    int k0s = z * dchunk;

    for (int k0 = k0s; k0 < k0s + dchunk; k0 += 64) {
        for (int idx = tid; idx < BN * 16; idx += 256) {
            int r = idx >> 4, c4 = (idx & 15) * 4;
            *(float4*)&Qs[r][c4] = *(const float4*)(qb + (size_t)r * d + k0 + c4);
            *(float4*)&Ks[r][c4] = *(const float4*)(kb + (size_t)r * d + k0 + c4);
        }
        __syncthreads();
#pragma unroll
        for (int kk2 = 0; kk2 < 32; kk2++) {
            ull q2[TN], k2[TN];
#pragma unroll
            for (int i = 0; i < TN; i++) q2[i] = *(const ull*)&Qs[r0 + i][2 * kk2];
#pragma unroll
            for (int j = 0; j < TN; j++) k2[j] = *(const ull*)&Ks[tx + 16 * j][2 * kk2];
#pragma unroll
            for (int i = 0; i < TN; i++)
#pragma unroll
                for (int j = 0; j < TN; j++) ffma2(acc[i][j], q2[i], k2[j]);
        }
        __syncthreads();
    }

    size_t base = ((size_t)(z * NBm + b)) * n * n;
#pragma unroll
    for (int i = 0; i < TN; i++)
#pragma unroll
        for (int j = 0; j < TN; j++)
            g_part[base + (size_t)(n0 + r0 + i) * n + (m0 + tx + 16 * j)] =
                hsum2(acc[i][j]);
}

// ============ reduce + softmax ============
__global__ __launch_bounds__(256)
void softmax_kernel(int n, int nsplit, float isd)
{
    __shared__ float sbuf[512];
    __shared__ float red[256];
    int row = blockIdx.x, b = blockIdx.y, tid = threadIdx.x;

    if (n <= 32) {
        int m = tid % n, zi = tid / n, tpm = 256 / n;
        float s = 0.f;
        for (int z = zi; z < nsplit; z += tpm)
            s += g_part[((size_t)(z * NBm + b) * n + row) * n + m];
        red[tid] = s;
        __syncthreads();
        if (tid < n) {
            float t = 0.f;
            for (int j = 0; j < tpm; j++) t += red[tid + j * n];
            sbuf[tid] = t * isd;
        }
    } else {
        for (int m = tid; m < n; m += 256) {
            float s = 0.f;
            for (int z = 0; z < nsplit; z++)
                s += g_part[((size_t)(z * NBm + b) * n + row) * n + m];
            sbuf[m] = s * isd;
        }
    }
    __syncthreads();

    float lm = -1e30f;
    for (int m = tid; m < n; m += 256) lm = fmaxf(lm, sbuf[m]);
    red[tid] = lm;
    __syncthreads();
    for (int s = 128; s > 0; s >>= 1) {
        if (tid < s) red[tid] = fmaxf(red[tid], red[tid + s]);
        __syncthreads();
    }
    float mx = red[0];
    __syncthreads();
    float ls = 0.f;
    for (int m = tid; m < n; m += 256) {
        float e = __expf(sbuf[m] - mx);
        sbuf[m] = e; ls += e;
    }
    red[tid] = ls;
    __syncthreads();
    for (int s = 128; s > 0; s >>= 1) {
        if (tid < s) red[tid] += red[tid + s];
        __syncthreads();
    }
    float inv = 1.0f / red[0];
    for (int m = tid; m < n; m += 256)
        g_attn[((size_t)b * n + row) * n + m] = sbuf[m] * inv;
}

// ============ AV (dense, windowed out) ============
template<int BN, int TN>
__global__ __launch_bounds__(256)
void av2_kernel(int n, int d, long long off_ll)
{
    __shared__ float As[BN][34];
    __shared__ float Vs[32][66];
    size_t off = (size_t)off_ll;
    int b = blockIdx.z, n0 = blockIdx.y * BN, e0 = blockIdx.x * 64;
    int tx = threadIdx.x, ty = threadIdx.y, tid = ty * 16 + tx;

    ull acc[TN][2];
#pragma unroll
    for (int i = 0; i < TN; i++) { acc[i][0] = 0ull; acc[i][1] = 0ull; }
    int r0 = ty * TN;

    const float* vb = g_vw + off + e0;

    for (int m0 = 0; m0 < n; m0 += 32) {
        for (int idx = tid; idx < BN * 8; idx += 256) {
            int r = idx >> 3, c4 = (idx & 7) * 4;
            float4 v = (m0 + c4 < n)
                ? *(const float4*)(g_attn + ((size_t)(b * n + n0 + r)) * n + m0 + c4)
                : make_float4(0.f, 0.f, 0.f, 0.f);
            As[r][c4] = v.x; As[r][c4 + 1] = v.y; As[r][c4 + 2] = v.z; As[r][c4 + 3] = v.w;
        }
        for (int idx = tid; idx < 512; idx += 256) {
            int mm = idx >> 4, e4 = (idx & 15) * 4;
            float4 v = (m0 + mm < n)
                ? *(const float4*)(vb + ((size_t)(b * n + m0 + mm)) * d + e4)
                : make_float4(0.f, 0.f, 0.f, 0.f);
            Vs[mm][e4] = v.x; Vs[mm][e4 + 1] = v.y; Vs[mm][e4 + 2] = v.z; Vs[mm][e4 + 3] = v.w;
        }
        __syncthreads();
#pragma unroll
        for (int kk = 0; kk < 32; kk++) {
            ull v2a = *(const ull*)&Vs[kk][2 * tx];
            ull v2b = *(const ull*)&Vs[kk][2 * tx + 32];
#pragma unroll
            for (int i = 0; i < TN; i++) {
                ull a2 = pack2(As[r0 + i][kk]);
                ffma2(acc[i][0], a2, v2a);
                ffma2(acc[i][1], a2, v2b);
            }
        }
        __syncthreads();
    }

    float* ob = g_ow + off;
#pragma unroll
    for (int i = 0; i < TN; i++) {
        size_t rb = ((size_t)(b * n + n0 + r0 + i)) * d + e0;
        *(float2*)(ob + rb + 2 * tx)      = *reinterpret_cast<float2*>(&acc[i][0]);
        *(float2*)(ob + rb + 2 * tx + 32) = *reinterpret_cast<float2*>(&acc[i][1]);
    }
}

// ============ unpack windowed -> channel-pair image layout ============
__global__ __launch_bounds__(256)
void unpack_kernel()
{
    int img = blockIdx.y, y = blockIdx.x;
    int tid = threadIdx.x;
    int x = tid & 127, half = tid >> 7;
    int b = img >> 3, t = img & 7;
    for (int c2 = half; c2 < 64; c2 += 2) {
        int oc = 2 * c2;
        int s = oc >> 5, lph = 7 - s;
        int n_s = 8 << (2 * s), d_s = 524288 >> (2 * s);
        int phm = (1 << lph) - 1;
        int oy = y >> lph, py = y & phm;
        int ox = x >> lph, px = x & phm;
        int tok = ((((t << s) + oy) << s) + ox);
        int e = ((((oc & 31) << lph) + py) << lph) + px;
        size_t a = (size_t)s * 8388608 + ((size_t)(b * n_s + tok)) * d_s + e;
        float2 v = make_float2(g_ow[a], g_ow[a + (1 << (2 * lph))]);
        g_ao2[((size_t)(img * 64 + c2)) * HWs + y * Wd + x] = v;
    }
}

// ============ pack conv3x3 weights ============
__global__ void wpack_kernel(const float* __restrict__ wo)
{
    int i = blockIdx.x * 256 + threadIdx.x;
    if (i >= 64 * 9 * 128) return;
    int oc = i & 127, tap = (i >> 7) % 9, c2 = i / (9 * 128);
    g_wt2[i] = make_float2(wo[((size_t)oc * 128 + 2 * c2) * 9 + tap],
                           wo[((size_t)oc * 128 + 2 * c2 + 1) * 9 + tap]);
}

// ============ conv3x3 + bias + relu (ffma2 over channel pairs) ============
__global__ __launch_bounds__(256)
void conv3x3_2_kernel(const float* __restrict__ bias, float* __restrict__ out)
{
    __shared__ float2 xr2[3][130];
    __shared__ float2 ws2[9][128];
    int img = blockIdx.y, y = blockIdx.x;
    int tx = threadIdx.x, ty = threadIdx.y, tid = ty * 16 + tx;

    ull acc[8][8];
#pragma unroll
    for (int i = 0; i < 8; i++)
#pragma unroll
        for (int j = 0; j < 8; j++) acc[i][j] = 0ull;

    for (int c2 = 0; c2 < 64; c2++) {
        const float2* in = g_ao2 + ((size_t)(img * 64 + c2)) * HWs;
        for (int i = tid; i < 390; i += 256) {
            int ry = i / 130, rx = i - ry * 130;
            int yy = y + ry - 1, xx = rx - 1;
            float2 v = make_float2(0.f, 0.f);
            if (yy >= 0 && yy < Hd && xx >= 0 && xx < Wd)
                v = in[(size_t)yy * Wd + xx];
            xr2[ry][rx] = v;
        }
        const float2* wp = g_wt2 + (size_t)c2 * 9 * 128;
        for (int i = tid; i < 1152; i += 256)
            ws2[i / 128][i & 127] = wp[i];
        __syncthreads();
#pragma unroll
        for (int ky = 0; ky < 3; ky++) {
#pragma unroll
            for (int kx = 0; kx < 3; kx++) {
                ull wr[8];
#pragma unroll
                for (int i = 0; i < 8; i++)
                    wr[i] = *(const ull*)&ws2[ky * 3 + kx][ty * 8 + i];
#pragma unroll
                for (int j = 0; j < 8; j++) {
                    ull xv = *(const ull*)&xr2[ky][tx + 16 * j + kx];
#pragma unroll
                    for (int i = 0; i < 8; i++) ffma2(acc[i][j], wr[i], xv);
                }
            }
        }
        __syncthreads();
    }

#pragma unroll
    for (int i = 0; i < 8; i++) {
        int oc = ty * 8 + i;
        float bv = bias[oc];
#pragma unroll
        for (int j = 0; j < 8; j++) {
            float v = hsum2(acc[i][j]) + bv;
            out[((size_t)(img * Cc + oc)) * HWs + (size_t)y * Wd + tx + 16 * j] =
                fmaxf(v, 0.f);
        }
    }
}

// ============ launch ============
extern "C" void kernel_launch(void* const* d_in, const int* in_sizes, int n_in,
                              void* d_out, int out_size)
{
    const float* x  = (const float*)d_in[0];
    const float* wq = (const float*)d_in[1];
    const float* bq = (const float*)d_in[2];
    const float* wk = (const float*)d_in[3];
    const float* bk = (const float*)d_in[4];
    const float* wv = (const float*)d_in[5];
    const float* bv = (const float*)d_in[6];
    const float* wo = (const float*)d_in[7];
    const float* bo = (const float*)d_in[8];
    float* out = (float*)d_out;

    dim3 blk(16, 16);

    wpack_kernel<<<(64 * 9 * 128 + 255) / 256, 256>>>(wo);
    conv1x1w_kernel<<<dim3(Hd, BT), blk>>>(x, wq, bq, 0);
    conv1x1w_kernel<<<dim3(Hd, BT), blk>>>(x, wk, bk, 1);
    conv1x1w_kernel<<<dim3(Hd, BT), blk>>>(x, wv, bv, 2);

    // scale 0: n=8, d=524288
    {
        float isd = 1.0f / sqrtf(524288.f);
        scores0_kernel<<<dim3(1024, NBm), 256>>>();
        softmax_kernel<<<dim3(8, NBm), 256>>>(8, 1024, isd);
        av2_kernel<8, 1><<<dim3(524288 / 64, 1, NBm), blk>>>(8, 524288, 0LL);
    }
    // scale 1: n=32, d=131072
    {
        long long off = 8388608LL;
        float isd = 1.0f / sqrtf(131072.f);
        scores2_kernel<32, 2><<<dim3(1, NBm, 256), blk>>>(32, 131072, off, 1, 512);
        softmax_kernel<<<dim3(32, NBm), 256>>>(32, 256, isd);
        av2_kernel<32, 2><<<dim3(131072 / 64, 1, NBm), blk>>>(32, 131072, off);
    }
    // scale 2: n=128, d=32768
    {
        long long off = 2LL * 8388608;
        float isd = 1.0f / sqrtf(32768.f);
        scores2_kernel<64, 4><<<dim3(4, NBm, 64), blk>>>(128, 32768, off, 2, 512);
        softmax_kernel<<<dim3(128, NBm), 256>>>(128, 64, isd);
        av2_kernel<64, 4><<<dim3(32768 / 64, 2, NBm), blk>>>(128, 32768, off);
    }
    // scale 3: n=512, d=8192
    {
        long long off = 3LL * 8388608;
        float isd = 1.0f / sqrtf(8192.f);
        scores2_kernel<64, 4><<<dim3(64, NBm, 16), blk>>>(512, 8192, off, 8, 512);
        softmax_kernel<<<dim3(512, NBm), 256>>>(512, 16, isd);
        av2_kernel<64, 4><<<dim3(8192 / 64, 8, NBm), blk>>>(512, 8192, off);
    }

    unpack_kernel<<<dim3(Hd, BT), 256>>>();
    conv3x3_2_kernel<<<dim3(Hd, BT), blk>>>(bo, out);

    (void)in_sizes; (void)n_in; (void)out_size;
}

// round 5
// speedup vs baseline: 2.1978x; 2.1375x over previous
#include <cuda_runtime.h>
#include <cuda_bf16.h>
#include <mma.h>
#include <math.h>

using namespace nvcuda;

typedef unsigned long long ull;
typedef unsigned int u32;

#define Cc 128
#define Hd 128
#define Wd 128
#define HWs 16384
#define BT 16
#define NBm 2

// ---------------- device scratch ----------------
__device__ float g_qw[(size_t)4 * 8388608];
__device__ float g_kw[(size_t)4 * 8388608];
__device__ float g_vw[(size_t)4 * 8388608];
__device__ float g_ow[(size_t)4 * 8388608];
__device__ float g_part[(size_t)1 << 24];
__device__ float g_attn[(size_t)NBm * 512 * 512];
__device__ __nv_bfloat16 g_xh[(size_t)33554432];
__device__ __nv_bfloat16 g_xl[(size_t)33554432];
__device__ __nv_bfloat16 g_ah[(size_t)33554432];
__device__ __nv_bfloat16 g_al[(size_t)33554432];
__device__ __nv_bfloat16 g_w3h[9 * 128 * 128];
__device__ __nv_bfloat16 g_w3l[9 * 128 * 128];
__device__ __nv_bfloat16 g_w1h[3 * 128 * 128];
__device__ __nv_bfloat16 g_w1l[3 * 128 * 128];

// ---------------- scalar helpers ----------------
__device__ __forceinline__ void ffma2(ull& d, ull a, ull b) {
    asm("fma.rn.f32x2 %0, %1, %2, %0;" : "+l"(d) : "l"(a), "l"(b));
}
__device__ __forceinline__ float hsum2(ull v) {
    float2 f = *reinterpret_cast<float2*>(&v);
    return f.x + f.y;
}
__device__ __forceinline__ ull pack2(float a) {
    ull r; asm("mov.b64 %0,{%1,%1};" : "=l"(r) : "f"(a)); return r;
}
__device__ __forceinline__ void bsplit(float v, __nv_bfloat16& h, __nv_bfloat16& l) {
    h = __float2bfloat16(v);
    l = __float2bfloat16(v - __bfloat162float(h));
}

typedef wmma::fragment<wmma::matrix_a, 16, 16, 16, __nv_bfloat16, wmma::row_major> FragA;
typedef wmma::fragment<wmma::matrix_b, 16, 16, 16, __nv_bfloat16, wmma::col_major> FragB;
typedef wmma::fragment<wmma::accumulator, 16, 16, 16, float> FragC;

// ============ prep: x -> channel-last bf16 hi/lo ============
__global__ __launch_bounds__(256)
void prep_x_kernel(const float* __restrict__ x)
{
    __shared__ float sb[64][130];
    int y = blockIdx.x, img = blockIdx.y, tid = threadIdx.x;
    for (int ch = 0; ch < 2; ch++) {
        for (int idx = tid; idx < 64 * 128; idx += 256) {
            int cl = idx >> 7, xp = idx & 127;
            sb[cl][xp] = x[((size_t)img * 128 + ch * 64 + cl) * HWs + y * 128 + xp];
        }
        __syncthreads();
        for (int idx = tid; idx < 64 * 128; idx += 256) {
            int px = idx >> 6, cl = idx & 63;
            __nv_bfloat16 h, l;
            bsplit(sb[cl][px], h, l);
            size_t o = (((size_t)img * 128 + y) * 128 + px) * 128 + ch * 64 + cl;
            g_xh[o] = h; g_xl[o] = l;
        }
        __syncthreads();
    }
}

// ============ prep: weights ============
__global__ void prep_w3_kernel(const float* __restrict__ wo)
{
    int i = blockIdx.x * 256 + threadIdx.x;
    if (i >= 9 * 128 * 128) return;
    int tap = i / 16384, r = i % 16384, oc = r >> 7, ic = r & 127;
    __nv_bfloat16 h, l;
    bsplit(wo[((size_t)oc * 128 + ic) * 9 + tap], h, l);
    size_t o = ((size_t)tap * 128 + oc) * 128 + ic;
    g_w3h[o] = h; g_w3l[o] = l;
}
__global__ void prep_w1_kernel(const float* __restrict__ wq,
                               const float* __restrict__ wk,
                               const float* __restrict__ wv)
{
    int i = blockIdx.x * 256 + threadIdx.x;
    if (i >= 3 * 16384) return;
    int o = i / 16384, r = i % 16384;
    const float* w = (o == 0) ? wq : (o == 1) ? wk : wv;
    __nv_bfloat16 h, l;
    bsplit(w[r], h, l);
    g_w1h[i] = h; g_w1l[i] = l;
}

// ============ conv1x1 via WMMA (one of q/k/v per z) ============
__global__ __launch_bounds__(256)
void conv1_wmma_kernel(const float* __restrict__ bq, const float* __restrict__ bk,
                       const float* __restrict__ bv)
{
    extern __shared__ __align__(16) char smem[];
    __nv_bfloat16* Ah = (__nv_bfloat16*)smem;                 // [128][136]
    __nv_bfloat16* Al = Ah + 128 * 136;
    __nv_bfloat16* Bh = Al + 128 * 136;
    __nv_bfloat16* Bl = Bh + 128 * 136;
    float* Cs = (float*)smem;                                  // overlays A

    int y = blockIdx.x, img = blockIdx.y, o = blockIdx.z;
    int tid = threadIdx.x, wid = tid >> 5;
    int wm = wid >> 1, wn = wid & 1;

    const float* bias = (o == 0) ? bq : (o == 1) ? bk : bv;
    float* dst = (o == 0) ? g_qw : (o == 1) ? g_kw : g_vw;

    // stage A [px][ic]
    {
        size_t base = (((size_t)img * 128 + y) * 128) * 128;
        for (int idx = tid; idx < 2048; idx += 256) {
            int row = idx >> 4, k8 = (idx & 15) << 3;
            *(uint4*)&Ah[row * 136 + k8] = *(const uint4*)(g_xh + base + row * 128 + k8);
            *(uint4*)&Al[row * 136 + k8] = *(const uint4*)(g_xl + base + row * 128 + k8);
        }
    }
    // stage B [oc][ic]
    {
        const __nv_bfloat16* bh = g_w1h + (size_t)o * 16384;
        const __nv_bfloat16* bl = g_w1l + (size_t)o * 16384;
        for (int idx = tid; idx < 2048; idx += 256) {
            int row = idx >> 4, k8 = (idx & 15) << 3;
            *(uint4*)&Bh[row * 136 + k8] = *(const uint4*)(bh + row * 128 + k8);
            *(uint4*)&Bl[row * 136 + k8] = *(const uint4*)(bl + row * 128 + k8);
        }
    }
    __syncthreads();

    FragC acc[2][4];
#pragma unroll
    for (int i = 0; i < 2; i++)
#pragma unroll
        for (int j = 0; j < 4; j++) wmma::fill_fragment(acc[i][j], 0.f);

    int px0 = wm * 32, oc0 = wn * 64;
#pragma unroll
    for (int kt = 0; kt < 8; kt++) {
        int k0 = kt * 16;
        FragA ah[2], al[2];
        FragB bh[4], bl[4];
#pragma unroll
        for (int i = 0; i < 2; i++) {
            wmma::load_matrix_sync(ah[i], &Ah[(px0 + 16 * i) * 136 + k0], 136);
            wmma::load_matrix_sync(al[i], &Al[(px0 + 16 * i) * 136 + k0], 136);
        }
#pragma unroll
        for (int j = 0; j < 4; j++) {
            wmma::load_matrix_sync(bh[j], &Bh[(oc0 + 16 * j) * 136 + k0], 136);
            wmma::load_matrix_sync(bl[j], &Bl[(oc0 + 16 * j) * 136 + k0], 136);
        }
#pragma unroll
        for (int i = 0; i < 2; i++)
#pragma unroll
            for (int j = 0; j < 4; j++) {
                wmma::mma_sync(acc[i][j], ah[i], bh[j], acc[i][j]);
                wmma::mma_sync(acc[i][j], ah[i], bl[j], acc[i][j]);
                wmma::mma_sync(acc[i][j], al[i], bh[j], acc[i][j]);
            }
    }
    __syncthreads();
#pragma unroll
    for (int i = 0; i < 2; i++)
#pragma unroll
        for (int j = 0; j < 4; j++)
            wmma::store_matrix_sync(&Cs[(px0 + 16 * i) * 136 + oc0 + 16 * j],
                                    acc[i][j], 136, wmma::mem_row_major);
    __syncthreads();

    // windowed scatter epilogue
    int b = img >> 3, t = img & 7;
    for (int idx = tid; idx < 16384; idx += 256) {
        int px = idx & 127, oc = idx >> 7;
        float v = Cs[px * 136 + oc] + bias[oc];
        int s = oc >> 5, lph = 7 - s;
        int phm = (1 << lph) - 1;
        int n_s = 8 << (2 * s), d_s = 524288 >> (2 * s);
        int oy = y >> lph, py = y & phm;
        int ox = px >> lph, pxm = px & phm;
        int tok = (((t << s) + oy) << s) + ox;
        int e = ((((oc & 31) << lph) + py) << lph) + pxm;
        dst[(size_t)s * 8388608 + ((size_t)(b * n_s + tok)) * d_s + e] = v;
    }
}

// ============ scale-0 scores (n=8, d=524288) ============
__global__ __launch_bounds__(256)
void scores0_kernel()
{
    __shared__ float Qs[8][516];
    __shared__ float Ks[8][516];
    __shared__ float sred[256];
    int z = blockIdx.x, b = blockIdx.y, tid = threadIdx.x;
    const int d = 524288;

    const float* qb = g_qw + ((size_t)(b * 8)) * d + z * 512;
    const float* kb = g_kw + ((size_t)(b * 8)) * d + z * 512;
    for (int idx = tid; idx < 1024; idx += 256) {
        int r = idx >> 7, c4 = (idx & 127) * 4;
        *(float4*)&Qs[r][c4] = *(const float4*)(qb + (size_t)r * d + c4);
        *(float4*)&Ks[r][c4] = *(const float4*)(kb + (size_t)r * d + c4);
    }
    __syncthreads();

    int rm = tid & 63, r = rm >> 3, m = rm & 7, kg = tid >> 6;
    ull acc = 0ull;
    int kb0 = kg * 128;
#pragma unroll
    for (int kk2 = 0; kk2 < 64; kk2++)
        ffma2(acc, *(const ull*)&Qs[r][kb0 + 2 * kk2], *(const ull*)&Ks[m][kb0 + 2 * kk2]);
    sred[tid] = hsum2(acc);
    __syncthreads();
    if (tid < 64)
        g_part[(size_t)(z * NBm + b) * 64 + tid] =
            sred[tid] + sred[tid + 64] + sred[tid + 128] + sred[tid + 192];
}

// ============ dense scores (scales 1-3), split-k ============
template<int BN, int TN>
__global__ __launch_bounds__(256)
void scores2_kernel(int n, int d, long long off_ll, int tilesM, int dchunk)
{
    __shared__ float Qs[BN][68];
    __shared__ float Ks[BN][68];
    size_t off = (size_t)off_ll;
    int b = blockIdx.y, z = blockIdx.z;
    int tn = blockIdx.x / tilesM, tm = blockIdx.x - tn * tilesM;
    int n0 = tn * BN, m0 = tm * BN;
    int tx = threadIdx.x, ty = threadIdx.y, tid = ty * 16 + tx;

    ull acc[TN][TN];
#pragma unroll
    for (int i = 0; i < TN; i++)
#pragma unroll
        for (int j = 0; j < TN; j++) acc[i][j] = 0ull;

    const float* qb = g_qw + off + ((size_t)(b * n + n0)) * d;
    const float* kb = g_kw + off + ((size_t)(b * n + m0)) * d;
    int r0 = ty * TN;
    int k0s = z * dchunk;

    for (int k0 = k0s; k0 < k0s + dchunk; k0 += 64) {
        for (int idx = tid; idx < BN * 16; idx += 256) {
            int r = idx >> 4, c4 = (idx & 15) * 4;
            *(float4*)&Qs[r][c4] = *(const float4*)(qb + (size_t)r * d + k0 + c4);
            *(float4*)&Ks[r][c4] = *(const float4*)(kb + (size_t)r * d + k0 + c4);
        }
        __syncthreads();
#pragma unroll
        for (int kk2 = 0; kk2 < 32; kk2++) {
            ull q2[TN], k2[TN];
#pragma unroll
            for (int i = 0; i < TN; i++) q2[i] = *(const ull*)&Qs[r0 + i][2 * kk2];
#pragma unroll
            for (int j = 0; j < TN; j++) k2[j] = *(const ull*)&Ks[tx + 16 * j][2 * kk2];
#pragma unroll
            for (int i = 0; i < TN; i++)
#pragma unroll
                for (int j = 0; j < TN; j++) ffma2(acc[i][j], q2[i], k2[j]);
        }
        __syncthreads();
    }

    size_t base = ((size_t)(z * NBm + b)) * n * n;
#pragma unroll
    for (int i = 0; i < TN; i++)
#pragma unroll
        for (int j = 0; j < TN; j++)
            g_part[base + (size_t)(n0 + r0 + i) * n + (m0 + tx + 16 * j)] =
                hsum2(acc[i][j]);
}

// ============ reduce + softmax ============
__global__ __launch_bounds__(256)
void softmax_kernel(int n, int nsplit, float isd)
{
    __shared__ float sbuf[512];
    __shared__ float red[256];
    int row = blockIdx.x, b = blockIdx.y, tid = threadIdx.x;

    if (n <= 32) {
        int m = tid % n, zi = tid / n, tpm = 256 / n;
        float s = 0.f;
        for (int z = zi; z < nsplit; z += tpm)
            s += g_part[((size_t)(z * NBm + b) * n + row) * n + m];
        red[tid] = s;
        __syncthreads();
        if (tid < n) {
            float t = 0.f;
            for (int j = 0; j < tpm; j++) t += red[tid + j * n];
            sbuf[tid] = t * isd;
        }
    } else {
        for (int m = tid; m < n; m += 256) {
            float s = 0.f;
            for (int z = 0; z < nsplit; z++)
                s += g_part[((size_t)(z * NBm + b) * n + row) * n + m];
            sbuf[m] = s * isd;
        }
    }
    __syncthreads();

    float lm = -1e30f;
    for (int m = tid; m < n; m += 256) lm = fmaxf(lm, sbuf[m]);
    red[tid] = lm;
    __syncthreads();
    for (int s = 128; s > 0; s >>= 1) {
        if (tid < s) red[tid] = fmaxf(red[tid], red[tid + s]);
        __syncthreads();
    }
    float mx = red[0];
    __syncthreads();
    float ls = 0.f;
    for (int m = tid; m < n; m += 256) {
        float e = __expf(sbuf[m] - mx);
        sbuf[m] = e; ls += e;
    }
    red[tid] = ls;
    __syncthreads();
    for (int s = 128; s > 0; s >>= 1) {
        if (tid < s) red[tid] += red[tid + s];
        __syncthreads();
    }
    float inv = 1.0f / red[0];
    for (int m = tid; m < n; m += 256)
        g_attn[((size_t)b * n + row) * n + m] = sbuf[m] * inv;
}

// ============ AV (dense, windowed out) ============
template<int BN, int TN>
__global__ __launch_bounds__(256)
void av2_kernel(int n, int d, long long off_ll)
{
    __shared__ float As[BN][34];
    __shared__ float Vs[32][66];
    size_t off = (size_t)off_ll;
    int b = blockIdx.z, n0 = blockIdx.y * BN, e0 = blockIdx.x * 64;
    int tx = threadIdx.x, ty = threadIdx.y, tid = ty * 16 + tx;

    ull acc[TN][2];
#pragma unroll
    for (int i = 0; i < TN; i++) { acc[i][0] = 0ull; acc[i][1] = 0ull; }
    int r0 = ty * TN;

    const float* vb = g_vw + off + e0;

    for (int m0 = 0; m0 < n; m0 += 32) {
        for (int idx = tid; idx < BN * 8; idx += 256) {
            int r = idx >> 3, c4 = (idx & 7) * 4;
            float4 v = (m0 + c4 < n)
                ? *(const float4*)(g_attn + ((size_t)(b * n + n0 + r)) * n + m0 + c4)
                : make_float4(0.f, 0.f, 0.f, 0.f);
            As[r][c4] = v.x; As[r][c4 + 1] = v.y; As[r][c4 + 2] = v.z; As[r][c4 + 3] = v.w;
        }
        for (int idx = tid; idx < 512; idx += 256) {
            int mm = idx >> 4, e4 = (idx & 15) * 4;
            float4 v = (m0 + mm < n)
                ? *(const float4*)(vb + ((size_t)(b * n + m0 + mm)) * d + e4)
                : make_float4(0.f, 0.f, 0.f, 0.f);
            Vs[mm][e4] = v.x; Vs[mm][e4 + 1] = v.y; Vs[mm][e4 + 2] = v.z; Vs[mm][e4 + 3] = v.w;
        }
        __syncthreads();
#pragma unroll
        for (int kk = 0; kk < 32; kk++) {
            ull v2a = *(const ull*)&Vs[kk][2 * tx];
            ull v2b = *(const ull*)&Vs[kk][2 * tx + 32];
#pragma unroll
            for (int i = 0; i < TN; i++) {
                ull a2 = pack2(As[r0 + i][kk]);
                ffma2(acc[i][0], a2, v2a);
                ffma2(acc[i][1], a2, v2b);
            }
        }
        __syncthreads();
    }

    float* ob = g_ow + off;
#pragma unroll
    for (int i = 0; i < TN; i++) {
        size_t rb = ((size_t)(b * n + n0 + r0 + i)) * d + e0;
        *(float2*)(ob + rb + 2 * tx)      = *reinterpret_cast<float2*>(&acc[i][0]);
        *(float2*)(ob + rb + 2 * tx + 32) = *reinterpret_cast<float2*>(&acc[i][1]);
    }
}

// ============ unpack windowed -> channel-last bf16 hi/lo ============
__global__ __launch_bounds__(256)
void unpack2_kernel()
{
    __shared__ float sbm[64][130];
    int y = blockIdx.x, img = blockIdx.y, tid = threadIdx.x;
    int b = img >> 3, t = img & 7;
    for (int ch = 0; ch < 2; ch++) {
        for (int idx = tid; idx < 64 * 128; idx += 256) {
            int cl = idx >> 7, xp = idx & 127;
            int c = ch * 64 + cl;
            int s = c >> 5, lph = 7 - s;
            int phm = (1 << lph) - 1;
            int n_s = 8 << (2 * s), d_s = 524288 >> (2 * s);
            int oy = y >> lph, py = y & phm;
            int ox = xp >> lph, pxm = xp & phm;
            int tok = ((((t << s) + oy) << s) + ox);
            int e = ((((c & 31) << lph) + py) << lph) + pxm;
            sbm[cl][xp] = g_ow[(size_t)s * 8388608 + ((size_t)(b * n_s + tok)) * d_s + e];
        }
        __syncthreads();
        for (int idx = tid; idx < 64 * 128; idx += 256) {
            int px = idx >> 6, cl = idx & 63;
            __nv_bfloat16 h, l;
            bsplit(sbm[cl][px], h, l);
            size_t o = (((size_t)img * 128 + y) * 128 + px) * 128 + ch * 64 + cl;
            g_ah[o] = h; g_al[o] = l;
        }
        __syncthreads();
    }
}

// ============ conv3x3 via WMMA (implicit GEMM) ============
__global__ __launch_bounds__(256)
void conv3_wmma_kernel(const float* __restrict__ bias, float* __restrict__ out)
{
    extern __shared__ __align__(16) char smem[];
    __nv_bfloat16* Ah = (__nv_bfloat16*)smem;                 // [130][136]
    __nv_bfloat16* Al = Ah + 130 * 136;
    __nv_bfloat16* Bh = Al + 130 * 136;                        // [128][136]
    __nv_bfloat16* Bl = Bh + 128 * 136;
    float* Cs = (float*)smem;

    int y = blockIdx.x, img = blockIdx.y;
    int tid = threadIdx.x, wid = tid >> 5;
    int wm = wid >> 1, wn = wid & 1;
    int px0 = wm * 32, oc0 = wn * 64;

    FragC acc[2][4];
#pragma unroll
    for (int i = 0; i < 2; i++)
#pragma unroll
        for (int j = 0; j < 4; j++) wmma::fill_fragment(acc[i][j], 0.f);

    for (int ky = 0; ky < 3; ky++) {
        int yy = y + ky - 1;
        bool yok = (yy >= 0 && yy < 128);
        __syncthreads();
        // stage A rows px=-1..128 -> index i=0..129
        size_t abase = (((size_t)img * 128 + (yok ? yy : 0)) * 128) * 128;
        for (int idx = tid; idx < 130 * 16; idx += 256) {
            int i = idx >> 4, k8 = (idx & 15) << 3;
            int px = i - 1;
            uint4 vh = make_uint4(0, 0, 0, 0), vl = make_uint4(0, 0, 0, 0);
            if (yok && px >= 0 && px < 128) {
                size_t o = abase + (size_t)px * 128 + k8;
                vh = *(const uint4*)(g_ah + o);
                vl = *(const uint4*)(g_al + o);
            }
            *(uint4*)&Ah[i * 136 + k8] = vh;
            *(uint4*)&Al[i * 136 + k8] = vl;
        }
        for (int kx = 0; kx < 3; kx++) {
            int tap = ky * 3 + kx;
            __syncthreads();
            const __nv_bfloat16* wh = g_w3h + (size_t)tap * 16384;
            const __nv_bfloat16* wl = g_w3l + (size_t)tap * 16384;
            for (int idx = tid; idx < 2048; idx += 256) {
                int row = idx >> 4, k8 = (idx & 15) << 3;
                *(uint4*)&Bh[row * 136 + k8] = *(const uint4*)(wh + row * 128 + k8);
                *(uint4*)&Bl[row * 136 + k8] = *(const uint4*)(wl + row * 128 + k8);
            }
            __syncthreads();
#pragma unroll
            for (int kt = 0; kt < 8; kt++) {
                int k0 = kt * 16;
                FragA ah[2], al[2];
                FragB bh[4], bl[4];
#pragma unroll
                for (int i = 0; i < 2; i++) {
                    wmma::load_matrix_sync(ah[i], &Ah[(px0 + 16 * i + kx) * 136 + k0], 136);
                    wmma::load_matrix_sync(al[i], &Al[(px0 + 16 * i + kx) * 136 + k0], 136);
                }
#pragma unroll
                for (int j = 0; j < 4; j++) {
                    wmma::load_matrix_sync(bh[j], &Bh[(oc0 + 16 * j) * 136 + k0], 136);
                    wmma::load_matrix_sync(bl[j], &Bl[(oc0 + 16 * j) * 136 + k0], 136);
                }
#pragma unroll
                for (int i = 0; i < 2; i++)
#pragma unroll
                    for (int j = 0; j < 4; j++) {
                        wmma::mma_sync(acc[i][j], ah[i], bh[j], acc[i][j]);
                        wmma::mma_sync(acc[i][j], ah[i], bl[j], acc[i][j]);
                        wmma::mma_sync(acc[i][j], al[i], bh[j], acc[i][j]);
                    }
            }
        }
    }
    __syncthreads();
#pragma unroll
    for (int i = 0; i < 2; i++)
#pragma unroll
        for (int j = 0; j < 4; j++)
            wmma::store_matrix_sync(&Cs[(px0 + 16 * i) * 136 + oc0 + 16 * j],
                                    acc[i][j], 136, wmma::mem_row_major);
    __syncthreads();

    for (int idx = tid; idx < 16384; idx += 256) {
        int px = idx & 127, oc = idx >> 7;
        float v = Cs[px * 136 + oc] + bias[oc];
        out[((size_t)img * 128 + oc) * HWs + (size_t)y * 128 + px] = fmaxf(v, 0.f);
    }
}

// ============ launch ============
extern "C" void kernel_launch(void* const* d_in, const int* in_sizes, int n_in,
                              void* d_out, int out_size)
{
    const float* x  = (const float*)d_in[0];
    const float* wq = (const float*)d_in[1];
    const float* bq = (const float*)d_in[2];
    const float* wk = (const float*)d_in[3];
    const float* bk = (const float*)d_in[4];
    const float* wv = (const float*)d_in[5];
    const float* bv = (const float*)d_in[6];
    const float* wo = (const float*)d_in[7];
    const float* bo = (const float*)d_in[8];
    float* out = (float*)d_out;

    const int smem1 = 4 * 128 * 136 * 2;                  // 139264
    const int smem3 = (2 * 130 * 136 + 2 * 128 * 136) * 2; // 140352
    cudaFuncSetAttribute(conv1_wmma_kernel,
                         cudaFuncAttributeMaxDynamicSharedMemorySize, smem1);
    cudaFuncSetAttribute(conv3_wmma_kernel,
                         cudaFuncAttributeMaxDynamicSharedMemorySize, smem3);

    dim3 blk(16, 16);

    prep_w3_kernel<<<(9 * 128 * 128 + 255) / 256, 256>>>(wo);
    prep_w1_kernel<<<(3 * 16384 + 255) / 256, 256>>>(wq, wk, wv);
    prep_x_kernel<<<dim3(Hd, BT), 256>>>(x);
    conv1_wmma_kernel<<<dim3(Hd, BT, 3), 256, smem1>>>(bq, bk, bv);

    // scale 0: n=8, d=524288
    {
        float isd = 1.0f / sqrtf(524288.f);
        scores0_kernel<<<dim3(1024, NBm), 256>>>();
        softmax_kernel<<<dim3(8, NBm), 256>>>(8, 1024, isd);
        av2_kernel<8, 1><<<dim3(524288 / 64, 1, NBm), blk>>>(8, 524288, 0LL);
    }
    // scale 1: n=32, d=131072
    {
        long long off = 8388608LL;
        float isd = 1.0f / sqrtf(131072.f);
        scores2_kernel<32, 2><<<dim3(1, NBm, 256), blk>>>(32, 131072, off, 1, 512);
        softmax_kernel<<<dim3(32, NBm), 256>>>(32, 256, isd);
        av2_kernel<32, 2><<<dim3(131072 / 64, 1, NBm), blk>>>(32, 131072, off);
    }
    // scale 2: n=128, d=32768
    {
        long long off = 2LL * 8388608;
        float isd = 1.0f / sqrtf(32768.f);
        scores2_kernel<64, 4><<<dim3(4, NBm, 64), blk>>>(128, 32768, off, 2, 512);
        softmax_kernel<<<dim3(128, NBm), 256>>>(128, 64, isd);
        av2_kernel<64, 4><<<dim3(32768 / 64, 2, NBm), blk>>>(128, 32768, off);
    }
    // scale 3: n=512, d=8192
    {
        long long off = 3LL * 8388608;
        float isd = 1.0f / sqrtf(8192.f);
        scores2_kernel<64, 4><<<dim3(64, NBm, 16), blk>>>(512, 8192, off, 8, 512);
        softmax_kernel<<<dim3(512, NBm), 256>>>(512, 16, isd);
        av2_kernel<64, 4><<<dim3(8192 / 64, 8, NBm), blk>>>(512, 8192, off);
    }

    unpack2_kernel<<<dim3(Hd, BT), 256>>>();
    conv3_wmma_kernel<<<dim3(Hd, BT), 256, smem3>>>(bo, out);

    (void)in_sizes; (void)n_in; (void)out_size;
}

// round 6
// speedup vs baseline: 2.4771x; 1.1271x over previous
#include <cuda_runtime.h>
#include <cuda_bf16.h>
#include <mma.h>
#include <math.h>

using namespace nvcuda;

typedef unsigned long long ull;
typedef unsigned int u32;

#define Cc 128
#define Hd 128
#define Wd 128
#define HWs 16384
#define BT 16
#define NBm 2

// ---------------- device scratch ----------------
__device__ float g_qw[(size_t)4 * 8388608];
__device__ float g_kw[(size_t)4 * 8388608];
__device__ float g_vw[(size_t)4 * 8388608];
__device__ float g_ow[(size_t)4 * 8388608];
__device__ float g_part[(size_t)1 << 24];
__device__ float g_attn[(size_t)NBm * 512 * 512];
__device__ __nv_bfloat16 g_xh[(size_t)33554432];
__device__ __nv_bfloat16 g_xl[(size_t)33554432];
__device__ __nv_bfloat16 g_ah[(size_t)33554432];
__device__ __nv_bfloat16 g_al[(size_t)33554432];
__device__ __nv_bfloat16 g_w3h[9 * 128 * 128];
__device__ __nv_bfloat16 g_w3l[9 * 128 * 128];
__device__ __nv_bfloat16 g_w1h[3 * 128 * 128];
__device__ __nv_bfloat16 g_w1l[3 * 128 * 128];

// ---------------- helpers ----------------
__device__ __forceinline__ void ffma2(ull& d, ull a, ull b) {
    asm("fma.rn.f32x2 %0, %1, %2, %0;" : "+l"(d) : "l"(a), "l"(b));
}
__device__ __forceinline__ float hsum2(ull v) {
    float2 f = *reinterpret_cast<float2*>(&v);
    return f.x + f.y;
}
__device__ __forceinline__ ull pack2(float a) {
    ull r; asm("mov.b64 %0,{%1,%1};" : "=l"(r) : "f"(a)); return r;
}
__device__ __forceinline__ void bsplit(float v, __nv_bfloat16& h, __nv_bfloat16& l) {
    h = __float2bfloat16(v);
    l = __float2bfloat16(v - __bfloat162float(h));
}
__device__ __forceinline__ u32 smem_u32(const void* p) {
    u32 a; asm("{ .reg .u64 t; cvta.to.shared.u64 t, %1; cvt.u32.u64 %0, t; }"
               : "=r"(a) : "l"(p));
    return a;
}
__device__ __forceinline__ void cpa16(u32 dst, const void* src) {
    asm volatile("cp.async.cg.shared.global [%0], [%1], 16;"
                 :: "r"(dst), "l"(src) : "memory");
}
#define CP_COMMIT() asm volatile("cp.async.commit_group;" ::: "memory")
#define CP_WAIT(n)  asm volatile("cp.async.wait_group %0;" :: "n"(n) : "memory")

typedef wmma::fragment<wmma::matrix_a, 16, 16, 16, __nv_bfloat16, wmma::row_major> FragA;
typedef wmma::fragment<wmma::matrix_b, 16, 16, 16, __nv_bfloat16, wmma::col_major> FragB;
typedef wmma::fragment<wmma::accumulator, 16, 16, 16, float> FragC;

// ============ prep: x -> channel-last bf16 hi/lo ============
__global__ __launch_bounds__(256)
void prep_x_kernel(const float* __restrict__ x)
{
    __shared__ float sb[64][130];
    int y = blockIdx.x, img = blockIdx.y, tid = threadIdx.x;
    for (int ch = 0; ch < 2; ch++) {
        for (int idx = tid; idx < 64 * 128; idx += 256) {
            int cl = idx >> 7, xp = idx & 127;
            sb[cl][xp] = x[((size_t)img * 128 + ch * 64 + cl) * HWs + y * 128 + xp];
        }
        __syncthreads();
        for (int idx = tid; idx < 64 * 128; idx += 256) {
            int px = idx >> 6, cl = idx & 63;
            __nv_bfloat16 h, l;
            bsplit(sb[cl][px], h, l);
            size_t o = (((size_t)img * 128 + y) * 128 + px) * 128 + ch * 64 + cl;
            g_xh[o] = h; g_xl[o] = l;
        }
        __syncthreads();
    }
}

// ============ prep: weights ============
__global__ void prep_w3_kernel(const float* __restrict__ wo)
{
    int i = blockIdx.x * 256 + threadIdx.x;
    if (i >= 9 * 128 * 128) return;
    int tap = i / 16384, r = i % 16384, oc = r >> 7, ic = r & 127;
    __nv_bfloat16 h, l;
    bsplit(wo[((size_t)oc * 128 + ic) * 9 + tap], h, l);
    size_t o = ((size_t)tap * 128 + oc) * 128 + ic;
    g_w3h[o] = h; g_w3l[o] = l;
}
__global__ void prep_w1_kernel(const float* __restrict__ wq,
                               const float* __restrict__ wk,
                               const float* __restrict__ wv)
{
    int i = blockIdx.x * 256 + threadIdx.x;
    if (i >= 3 * 16384) return;
    int o = i / 16384, r = i % 16384;
    const float* w = (o == 0) ? wq : (o == 1) ? wk : wv;
    __nv_bfloat16 h, l;
    bsplit(w[r], h, l);
    g_w1h[i] = h; g_w1l[i] = l;
}

// ============ conv1x1 fused q/k/v via WMMA + cp.async pipeline ============
// smem bytes: AH 0..34816, AL 34816..69632, Bbuf0 69632 (H) +34816 (L),
//             Bbuf1 139264 (H) +34816 (L). total 208896. C overlays Bbuf[o&1].
__global__ __launch_bounds__(256)
void conv1_fused_kernel(const float* __restrict__ bq, const float* __restrict__ bk,
                        const float* __restrict__ bv)
{
    extern __shared__ __align__(16) char smem[];
    u32 sb = smem_u32(smem);
    const u32 AH = 0, AL = 34816;
    const u32 BB0 = 69632, BB1 = 139264;

    int y = blockIdx.x, img = blockIdx.y;
    int tid = threadIdx.x, wid = tid >> 5;
    int wm = wid & 3, wn = wid >> 2;
    int px0 = wm * 32, oc0 = wn * 64;

    // stage A (hi/lo) + B0 via cp.async
    {
        size_t base = (((size_t)img * 128 + y) * 128) * 128;
        for (int idx = tid; idx < 2048; idx += 256) {
            int row = idx >> 4, k8 = (idx & 15) << 3;
            u32 d = (u32)(row * 136 + k8) * 2;
            cpa16(sb + AH + d, g_xh + base + row * 128 + k8);
            cpa16(sb + AL + d, g_xl + base + row * 128 + k8);
        }
        for (int idx = tid; idx < 2048; idx += 256) {
            int row = idx >> 4, k8 = (idx & 15) << 3;
            u32 d = (u32)(row * 136 + k8) * 2;
            cpa16(sb + BB0 + d,         g_w1h + row * 128 + k8);
            cpa16(sb + BB0 + 34816 + d, g_w1l + row * 128 + k8);
        }
        CP_COMMIT();
    }

    int b = img >> 3, t = img & 7;

    for (int o = 0; o < 3; o++) {
        CP_WAIT(0);
        __syncthreads();
        u32 BB = (o & 1) ? BB1 : BB0;
        if (o < 2) {
            u32 BBn = ((o + 1) & 1) ? BB1 : BB0;
            const __nv_bfloat16* wh = g_w1h + (size_t)(o + 1) * 16384;
            const __nv_bfloat16* wl = g_w1l + (size_t)(o + 1) * 16384;
            for (int idx = tid; idx < 2048; idx += 256) {
                int row = idx >> 4, k8 = (idx & 15) << 3;
                u32 d = (u32)(row * 136 + k8) * 2;
                cpa16(sb + BBn + d,         wh + row * 128 + k8);
                cpa16(sb + BBn + 34816 + d, wl + row * 128 + k8);
            }
            CP_COMMIT();
        }

        const __nv_bfloat16* sAh = (const __nv_bfloat16*)(smem + AH);
        const __nv_bfloat16* sAl = (const __nv_bfloat16*)(smem + AL);
        const __nv_bfloat16* sBh = (const __nv_bfloat16*)(smem + BB);
        const __nv_bfloat16* sBl = (const __nv_bfloat16*)(smem + BB + 34816);

        FragC acc[2][4];
#pragma unroll
        for (int i = 0; i < 2; i++)
#pragma unroll
            for (int j = 0; j < 4; j++) wmma::fill_fragment(acc[i][j], 0.f);

#pragma unroll
        for (int kt = 0; kt < 8; kt++) {
            int k0 = kt * 16;
            FragA ah[2], al[2];
            FragB bh[4], bl[4];
#pragma unroll
            for (int i = 0; i < 2; i++) {
                wmma::load_matrix_sync(ah[i], &sAh[(px0 + 16 * i) * 136 + k0], 136);
                wmma::load_matrix_sync(al[i], &sAl[(px0 + 16 * i) * 136 + k0], 136);
            }
#pragma unroll
            for (int j = 0; j < 4; j++) {
                wmma::load_matrix_sync(bh[j], &sBh[(oc0 + 16 * j) * 136 + k0], 136);
                wmma::load_matrix_sync(bl[j], &sBl[(oc0 + 16 * j) * 136 + k0], 136);
            }
#pragma unroll
            for (int i = 0; i < 2; i++)
#pragma unroll
                for (int j = 0; j < 4; j++) {
                    wmma::mma_sync(acc[i][j], ah[i], bh[j], acc[i][j]);
                    wmma::mma_sync(acc[i][j], ah[i], bl[j], acc[i][j]);
                    wmma::mma_sync(acc[i][j], al[i], bh[j], acc[i][j]);
                }
        }
        __syncthreads();

        float* Cs = (float*)(smem + BB);
#pragma unroll
        for (int i = 0; i < 2; i++)
#pragma unroll
            for (int j = 0; j < 4; j++)
                wmma::store_matrix_sync(&Cs[(px0 + 16 * i) * 132 + oc0 + 16 * j],
                                        acc[i][j], 132, wmma::mem_row_major);
        __syncthreads();

        const float* bias = (o == 0) ? bq : (o == 1) ? bk : bv;
        float* dst = (o == 0) ? g_qw : (o == 1) ? g_kw : g_vw;
        for (int idx = tid; idx < 16384; idx += 256) {
            int px = idx & 127, oc = idx >> 7;
            float v = Cs[px * 132 + oc] + bias[oc];
            int s = oc >> 5, lph = 7 - s;
            int phm = (1 << lph) - 1;
            int n_s = 8 << (2 * s), d_s = 524288 >> (2 * s);
            int oy = y >> lph, py = y & phm;
            int ox = px >> lph, pxm = px & phm;
            int tok = (((t << s) + oy) << s) + ox;
            int e = ((((oc & 31) << lph) + py) << lph) + pxm;
            dst[(size_t)s * 8388608 + ((size_t)(b * n_s + tok)) * d_s + e] = v;
        }
    }
}

// ============ scale-0 scores (n=8, d=524288) ============
__global__ __launch_bounds__(256)
void scores0_kernel()
{
    __shared__ float Qs[8][516];
    __shared__ float Ks[8][516];
    __shared__ float sred[256];
    int z = blockIdx.x, b = blockIdx.y, tid = threadIdx.x;
    const int d = 524288;

    const float* qb = g_qw + ((size_t)(b * 8)) * d + z * 512;
    const float* kb = g_kw + ((size_t)(b * 8)) * d + z * 512;
    for (int idx = tid; idx < 1024; idx += 256) {
        int r = idx >> 7, c4 = (idx & 127) * 4;
        *(float4*)&Qs[r][c4] = *(const float4*)(qb + (size_t)r * d + c4);
        *(float4*)&Ks[r][c4] = *(const float4*)(kb + (size_t)r * d + c4);
    }
    __syncthreads();

    int rm = tid & 63, r = rm >> 3, m = rm & 7, kg = tid >> 6;
    ull acc = 0ull;
    int kb0 = kg * 128;
#pragma unroll
    for (int kk2 = 0; kk2 < 64; kk2++)
        ffma2(acc, *(const ull*)&Qs[r][kb0 + 2 * kk2], *(const ull*)&Ks[m][kb0 + 2 * kk2]);
    sred[tid] = hsum2(acc);
    __syncthreads();
    if (tid < 64)
        g_part[(size_t)(z * NBm + b) * 64 + tid] =
            sred[tid] + sred[tid + 64] + sred[tid + 128] + sred[tid + 192];
}

// ============ dense scores (scales 1-3), split-k ============
template<int BN, int TN>
__global__ __launch_bounds__(256)
void scores2_kernel(int n, int d, long long off_ll, int tilesM, int dchunk)
{
    __shared__ float Qs[BN][68];
    __shared__ float Ks[BN][68];
    size_t off = (size_t)off_ll;
    int b = blockIdx.y, z = blockIdx.z;
    int tn = blockIdx.x / tilesM, tm = blockIdx.x - tn * tilesM;
    int n0 = tn * BN, m0 = tm * BN;
    int tx = threadIdx.x, ty = threadIdx.y, tid = ty * 16 + tx;

    ull acc[TN][TN];
#pragma unroll
    for (int i = 0; i < TN; i++)
#pragma unroll
        for (int j = 0; j < TN; j++) acc[i][j] = 0ull;

    const float* qb = g_qw + off + ((size_t)(b * n + n0)) * d;
    const float* kb = g_kw + off + ((size_t)(b * n + m0)) * d;
    int r0 = ty * TN;
    int k0s = z * dchunk;

    for (int k0 = k0s; k0 < k0s + dchunk; k0 += 64) {
        for (int idx = tid; idx < BN * 16; idx += 256) {
            int r = idx >> 4, c4 = (idx & 15) * 4;
            *(float4*)&Qs[r][c4] = *(const float4*)(qb + (size_t)r * d + k0 + c4);
            *(float4*)&Ks[r][c4] = *(const float4*)(kb + (size_t)r * d + k0 + c4);
        }
        __syncthreads();
#pragma unroll
        for (int kk2 = 0; kk2 < 32; kk2++) {
            ull q2[TN], k2[TN];
#pragma unroll
            for (int i = 0; i < TN; i++) q2[i] = *(const ull*)&Qs[r0 + i][2 * kk2];
#pragma unroll
            for (int j = 0; j < TN; j++) k2[j] = *(const ull*)&Ks[tx + 16 * j][2 * kk2];
#pragma unroll
            for (int i = 0; i < TN; i++)
#pragma unroll
                for (int j = 0; j < TN; j++) ffma2(acc[i][j], q2[i], k2[j]);
        }
        __syncthreads();
    }

    size_t base = ((size_t)(z * NBm + b)) * n * n;
#pragma unroll
    for (int i = 0; i < TN; i++)
#pragma unroll
        for (int j = 0; j < TN; j++)
            g_part[base + (size_t)(n0 + r0 + i) * n + (m0 + tx + 16 * j)] =
                hsum2(acc[i][j]);
}

// ============ reduce + softmax ============
__global__ __launch_bounds__(256)
void softmax_kernel(int n, int nsplit, float isd)
{
    __shared__ float sbuf[512];
    __shared__ float red[256];
    int row = blockIdx.x, b = blockIdx.y, tid = threadIdx.x;

    if (n <= 32) {
        int m = tid % n, zi = tid / n, tpm = 256 / n;
        float s = 0.f;
        for (int z = zi; z < nsplit; z += tpm)
            s += g_part[((size_t)(z * NBm + b) * n + row) * n + m];
        red[tid] = s;
        __syncthreads();
        if (tid < n) {
            float t = 0.f;
            for (int j = 0; j < tpm; j++) t += red[tid + j * n];
            sbuf[tid] = t * isd;
        }
    } else {
        for (int m = tid; m < n; m += 256) {
            float s = 0.f;
            for (int z = 0; z < nsplit; z++)
                s += g_part[((size_t)(z * NBm + b) * n + row) * n + m];
            sbuf[m] = s * isd;
        }
    }
    __syncthreads();

    float lm = -1e30f;
    for (int m = tid; m < n; m += 256) lm = fmaxf(lm, sbuf[m]);
    red[tid] = lm;
    __syncthreads();
    for (int s = 128; s > 0; s >>= 1) {
        if (tid < s) red[tid] = fmaxf(red[tid], red[tid + s]);
        __syncthreads();
    }
    float mx = red[0];
    __syncthreads();
    float ls = 0.f;
    for (int m = tid; m < n; m += 256) {
        float e = __expf(sbuf[m] - mx);
        sbuf[m] = e; ls += e;
    }
    red[tid] = ls;
    __syncthreads();
    for (int s = 128; s > 0; s >>= 1) {
        if (tid < s) red[tid] += red[tid + s];
        __syncthreads();
    }
    float inv = 1.0f / red[0];
    for (int m = tid; m < n; m += 256)
        g_attn[((size_t)b * n + row) * n + m] = sbuf[m] * inv;
}

// ============ AV (dense, windowed out) ============
template<int BN, int TN>
__global__ __launch_bounds__(256)
void av2_kernel(int n, int d, long long off_ll)
{
    __shared__ float As[BN][34];
    __shared__ float Vs[32][66];
    size_t off = (size_t)off_ll;
    int b = blockIdx.z, n0 = blockIdx.y * BN, e0 = blockIdx.x * 64;
    int tx = threadIdx.x, ty = threadIdx.y, tid = ty * 16 + tx;

    ull acc[TN][2];
#pragma unroll
    for (int i = 0; i < TN; i++) { acc[i][0] = 0ull; acc[i][1] = 0ull; }
    int r0 = ty * TN;

    const float* vb = g_vw + off + e0;

    for (int m0 = 0; m0 < n; m0 += 32) {
        for (int idx = tid; idx < BN * 8; idx += 256) {
            int r = idx >> 3, c4 = (idx & 7) * 4;
            float4 v = (m0 + c4 < n)
                ? *(const float4*)(g_attn + ((size_t)(b * n + n0 + r)) * n + m0 + c4)
                : make_float4(0.f, 0.f, 0.f, 0.f);
            As[r][c4] = v.x; As[r][c4 + 1] = v.y; As[r][c4 + 2] = v.z; As[r][c4 + 3] = v.w;
        }
        for (int idx = tid; idx < 512; idx += 256) {
            int mm = idx >> 4, e4 = (idx & 15) * 4;
            float4 v = (m0 + mm < n)
                ? *(const float4*)(vb + ((size_t)(b * n + m0 + mm)) * d + e4)
                : make_float4(0.f, 0.f, 0.f, 0.f);
            Vs[mm][e4] = v.x; Vs[mm][e4 + 1] = v.y; Vs[mm][e4 + 2] = v.z; Vs[mm][e4 + 3] = v.w;
        }
        __syncthreads();
#pragma unroll
        for (int kk = 0; kk < 32; kk++) {
            ull v2a = *(const ull*)&Vs[kk][2 * tx];
            ull v2b = *(const ull*)&Vs[kk][2 * tx + 32];
#pragma unroll
            for (int i = 0; i < TN; i++) {
                ull a2 = pack2(As[r0 + i][kk]);
                ffma2(acc[i][0], a2, v2a);
                ffma2(acc[i][1], a2, v2b);
            }
        }
        __syncthreads();
    }

    float* ob = g_ow + off;
#pragma unroll
    for (int i = 0; i < TN; i++) {
        size_t rb = ((size_t)(b * n + n0 + r0 + i)) * d + e0;
        *(float2*)(ob + rb + 2 * tx)      = *reinterpret_cast<float2*>(&acc[i][0]);
        *(float2*)(ob + rb + 2 * tx + 32) = *reinterpret_cast<float2*>(&acc[i][1]);
    }
}

// ============ unpack windowed -> channel-last bf16 hi/lo ============
__global__ __launch_bounds__(256)
void unpack2_kernel()
{
    __shared__ float sbm[64][130];
    int y = blockIdx.x, img = blockIdx.y, tid = threadIdx.x;
    int b = img >> 3, t = img & 7;
    for (int ch = 0; ch < 2; ch++) {
        for (int idx = tid; idx < 64 * 128; idx += 256) {
            int cl = idx >> 7, xp = idx & 127;
            int c = ch * 64 + cl;
            int s = c >> 5, lph = 7 - s;
            int phm = (1 << lph) - 1;
            int n_s = 8 << (2 * s), d_s = 524288 >> (2 * s);
            int oy = y >> lph, py = y & phm;
            int ox = xp >> lph, pxm = xp & phm;
            int tok = ((((t << s) + oy) << s) + ox);
            int e = ((((c & 31) << lph) + py) << lph) + pxm;
            sbm[cl][xp] = g_ow[(size_t)s * 8388608 + ((size_t)(b * n_s + tok)) * d_s + e];
        }
        __syncthreads();
        for (int idx = tid; idx < 64 * 128; idx += 256) {
            int px = idx >> 6, cl = idx & 63;
            __nv_bfloat16 h, l;
            bsplit(sbm[cl][px], h, l);
            size_t o = (((size_t)img * 128 + y) * 128 + px) * 128 + ch * 64 + cl;
            g_ah[o] = h; g_al[o] = l;
        }
        __syncthreads();
    }
}

// ============ conv3x3 via WMMA + cp.async tap pipeline ============
// smem: AH 0..35360, AL 35360..70720, B0H 70720, B0L 105536, B1H 140352,
//       B1L 175168, end 209984. C overlays B0 region.
__global__ __launch_bounds__(256)
void conv3_pipe_kernel(const float* __restrict__ bias, float* __restrict__ out)
{
    extern __shared__ __align__(16) char smem[];
    u32 sb = smem_u32(smem);
    const u32 AH = 0, AL = 35360;
    const u32 BB0 = 70720, BB1 = 140352;

    int y = blockIdx.x, img = blockIdx.y;
    int tid = threadIdx.x, wid = tid >> 5;
    int wm = wid & 3, wn = wid >> 2;
    int px0 = wm * 32, oc0 = wn * 64;

    FragC acc[2][4];
#pragma unroll
    for (int i = 0; i < 2; i++)
#pragma unroll
        for (int j = 0; j < 4; j++) wmma::fill_fragment(acc[i][j], 0.f);

    // prefetch B(tap 0)
    for (int idx = tid; idx < 2048; idx += 256) {
        int row = idx >> 4, k8 = (idx & 15) << 3;
        u32 d = (u32)(row * 136 + k8) * 2;
        cpa16(sb + BB0 + d,         g_w3h + row * 128 + k8);
        cpa16(sb + BB0 + 34816 + d, g_w3l + row * 128 + k8);
    }
    CP_COMMIT();

    for (int tp = 0; tp < 9; tp++) {
        int ky = tp / 3, kx = tp - ky * 3;
        CP_WAIT(0);
        __syncthreads();
        if (kx == 0) {
            // stage A for row yy = y + ky - 1, rows i=0..129 (px = i-1)
            int yy = y + ky - 1;
            bool yok = (yy >= 0 && yy < 128);
            size_t abase = (((size_t)img * 128 + (yok ? yy : 0)) * 128) * 128;
            for (int idx = tid; idx < 2080; idx += 256) {
                int i = idx >> 4, k8 = (idx & 15) << 3;
                int px = i - 1;
                u32 d = (u32)(i * 136 + k8) * 2;
                if (yok && px >= 0 && px < 128) {
                    size_t o = abase + (size_t)px * 128 + k8;
                    cpa16(sb + AH + d, g_ah + o);
                    cpa16(sb + AL + d, g_al + o);
                } else {
                    uint4 z = make_uint4(0, 0, 0, 0);
                    *(uint4*)(smem + AH + d) = z;
                    *(uint4*)(smem + AL + d) = z;
                }
            }
            CP_COMMIT();
        }
        if (tp < 8) {
            u32 BBn = ((tp + 1) & 1) ? BB1 : BB0;
            const __nv_bfloat16* wh = g_w3h + (size_t)(tp + 1) * 16384;
            const __nv_bfloat16* wl = g_w3l + (size_t)(tp + 1) * 16384;
            for (int idx = tid; idx < 2048; idx += 256) {
                int row = idx >> 4, k8 = (idx & 15) << 3;
                u32 d = (u32)(row * 136 + k8) * 2;
                cpa16(sb + BBn + d,         wh + row * 128 + k8);
                cpa16(sb + BBn + 34816 + d, wl + row * 128 + k8);
            }
            CP_COMMIT();
        }
        if (kx == 0) {
            // need A done; B(tp+1) may remain outstanding (1 group)
            if (tp < 8) { CP_WAIT(1); } else { CP_WAIT(0); }
            __syncthreads();
        }

        u32 BB = (tp & 1) ? BB1 : BB0;
        const __nv_bfloat16* sAh = (const __nv_bfloat16*)(smem + AH);
        const __nv_bfloat16* sAl = (const __nv_bfloat16*)(smem + AL);
        const __nv_bfloat16* sBh = (const __nv_bfloat16*)(smem + BB);
        const __nv_bfloat16* sBl = (const __nv_bfloat16*)(smem + BB + 34816);

#pragma unroll
        for (int kt = 0; kt < 8; kt++) {
            int k0 = kt * 16;
            FragA ah[2], al[2];
            FragB bh[4], bl[4];
#pragma unroll
            for (int i = 0; i < 2; i++) {
                wmma::load_matrix_sync(ah[i], &sAh[(px0 + 16 * i + kx) * 136 + k0], 136);
                wmma::load_matrix_sync(al[i], &sAl[(px0 + 16 * i + kx) * 136 + k0], 136);
            }
#pragma unroll
            for (int j = 0; j < 4; j++) {
                wmma::load_matrix_sync(bh[j], &sBh[(oc0 + 16 * j) * 136 + k0], 136);
                wmma::load_matrix_sync(bl[j], &sBl[(oc0 + 16 * j) * 136 + k0], 136);
            }
#pragma unroll
            for (int i = 0; i < 2; i++)
#pragma unroll
                for (int j = 0; j < 4; j++) {
                    wmma::mma_sync(acc[i][j], ah[i], bh[j], acc[i][j]);
                    wmma::mma_sync(acc[i][j], ah[i], bl[j], acc[i][j]);
                    wmma::mma_sync(acc[i][j], al[i], bh[j], acc[i][j]);
                }
        }
        __syncthreads();
    }

    float* Cs = (float*)(smem + BB0);
#pragma unroll
    for (int i = 0; i < 2; i++)
#pragma unroll
        for (int j = 0; j < 4; j++)
            wmma::store_matrix_sync(&Cs[(px0 + 16 * i) * 132 + oc0 + 16 * j],
                                    acc[i][j], 132, wmma::mem_row_major);
    __syncthreads();

    for (int idx = tid; idx < 16384; idx += 256) {
        int px = idx & 127, oc = idx >> 7;
        float v = Cs[px * 132 + oc] + bias[oc];
        out[((size_t)img * 128 + oc) * HWs + (size_t)y * 128 + px] = fmaxf(v, 0.f);
    }
}

// ============ launch ============
extern "C" void kernel_launch(void* const* d_in, const int* in_sizes, int n_in,
                              void* d_out, int out_size)
{
    const float* x  = (const float*)d_in[0];
    const float* wq = (const float*)d_in[1];
    const float* bq = (const float*)d_in[2];
    const float* wk = (const float*)d_in[3];
    const float* bk = (const float*)d_in[4];
    const float* wv = (const float*)d_in[5];
    const float* bv = (const float*)d_in[6];
    const float* wo = (const float*)d_in[7];
    const float* bo = (const float*)d_in[8];
    float* out = (float*)d_out;

    const int smem1 = 208896;
    const int smem3 = 209984;
    cudaFuncSetAttribute(conv1_fused_kernel,
                         cudaFuncAttributeMaxDynamicSharedMemorySize, smem1);
    cudaFuncSetAttribute(conv3_pipe_kernel,
                         cudaFuncAttributeMaxDynamicSharedMemorySize, smem3);

    dim3 blk(16, 16);

    prep_w3_kernel<<<(9 * 128 * 128 + 255) / 256, 256>>>(wo);
    prep_w1_kernel<<<(3 * 16384 + 255) / 256, 256>>>(wq, wk, wv);
    prep_x_kernel<<<dim3(Hd, BT), 256>>>(x);
    conv1_fused_kernel<<<dim3(Hd, BT), 256, smem1>>>(bq, bk, bv);

    // scale 0: n=8, d=524288
    {
        float isd = 1.0f / sqrtf(524288.f);
        scores0_kernel<<<dim3(1024, NBm), 256>>>();
        softmax_kernel<<<dim3(8, NBm), 256>>>(8, 1024, isd);
        av2_kernel<8, 1><<<dim3(524288 / 64, 1, NBm), blk>>>(8, 524288, 0LL);
    }
    // scale 1: n=32, d=131072
    {
        long long off = 8388608LL;
        float isd = 1.0f / sqrtf(131072.f);
        scores2_kernel<32, 2><<<dim3(1, NBm, 256), blk>>>(32, 131072, off, 1, 512);
        softmax_kernel<<<dim3(32, NBm), 256>>>(32, 256, isd);
        av2_kernel<32, 2><<<dim3(131072 / 64, 1, NBm), blk>>>(32, 131072, off);
    }
    // scale 2: n=128, d=32768
    {
        long long off = 2LL * 8388608;
        float isd = 1.0f / sqrtf(32768.f);
        scores2_kernel<64, 4><<<dim3(4, NBm, 64), blk>>>(128, 32768, off, 2, 512);
        softmax_kernel<<<dim3(128, NBm), 256>>>(128, 64, isd);
        av2_kernel<64, 4><<<dim3(32768 / 64, 2, NBm), blk>>>(128, 32768, off);
    }
    // scale 3: n=512, d=8192
    {
        long long off = 3LL * 8388608;
        float isd = 1.0f / sqrtf(8192.f);
        scores2_kernel<64, 4><<<dim3(64, NBm, 16), blk>>>(512, 8192, off, 8, 512);
        softmax_kernel<<<dim3(512, NBm), 256>>>(512, 16, isd);
        av2_kernel<64, 4><<<dim3(8192 / 64, 8, NBm), blk>>>(512, 8192, off);
    }

    unpack2_kernel<<<dim3(Hd, BT), 256>>>();
    conv3_pipe_kernel<<<dim3(Hd, BT), 256, smem3>>>(bo, out);

    (void)in_sizes; (void)n_in; (void)out_size;
}

// round 7
// speedup vs baseline: 2.8519x; 1.1513x over previous
#include <cuda_runtime.h>
#include <cuda_bf16.h>
#include <mma.h>
#include <math.h>

using namespace nvcuda;

typedef unsigned long long ull;
typedef unsigned int u32;

#define Cc 128
#define Hd 128
#define Wd 128
#define HWs 16384
#define BT 16
#define NBm 2

// ---------------- device scratch ----------------
__device__ float g_qw[(size_t)2 * 8388608];   // scales 0,1 fp32
__device__ float g_kw[(size_t)2 * 8388608];
__device__ float g_vw[(size_t)2 * 8388608];
__device__ float g_ow[(size_t)4 * 8388608];
__device__ float g_part[(size_t)1 << 24];
__device__ float g_attn[(size_t)NBm * 512 * 512];
__device__ __nv_bfloat16 g_ath[(size_t)NBm * 512 * 512];
__device__ __nv_bfloat16 g_atl[(size_t)NBm * 512 * 512];
__device__ __nv_bfloat16 g_qh[(size_t)2 * 8388608];   // scales 2,3 bf16 hi/lo
__device__ __nv_bfloat16 g_ql[(size_t)2 * 8388608];
__device__ __nv_bfloat16 g_kh[(size_t)2 * 8388608];
__device__ __nv_bfloat16 g_kl[(size_t)2 * 8388608];
__device__ __nv_bfloat16 g_vh[(size_t)2 * 8388608];
__device__ __nv_bfloat16 g_vl[(size_t)2 * 8388608];
__device__ __nv_bfloat16 g_xh[(size_t)33554432];
__device__ __nv_bfloat16 g_xl[(size_t)33554432];
__device__ __nv_bfloat16 g_ah[(size_t)33554432];
__device__ __nv_bfloat16 g_al[(size_t)33554432];
__device__ __nv_bfloat16 g_w3h[9 * 128 * 128];
__device__ __nv_bfloat16 g_w3l[9 * 128 * 128];
__device__ __nv_bfloat16 g_w1h[3 * 128 * 128];
__device__ __nv_bfloat16 g_w1l[3 * 128 * 128];

// ---------------- helpers ----------------
__device__ __forceinline__ void ffma2(ull& d, ull a, ull b) {
    asm("fma.rn.f32x2 %0, %1, %2, %0;" : "+l"(d) : "l"(a), "l"(b));
}
__device__ __forceinline__ float hsum2(ull v) {
    float2 f = *reinterpret_cast<float2*>(&v);
    return f.x + f.y;
}
__device__ __forceinline__ ull pack2(float a) {
    ull r; asm("mov.b64 %0,{%1,%1};" : "=l"(r) : "f"(a)); return r;
}
__device__ __forceinline__ void bsplit(float v, __nv_bfloat16& h, __nv_bfloat16& l) {
    h = __float2bfloat16(v);
    l = __float2bfloat16(v - __bfloat162float(h));
}
__device__ __forceinline__ u32 smem_u32(const void* p) {
    u32 a; asm("{ .reg .u64 t; cvta.to.shared.u64 t, %1; cvt.u32.u64 %0, t; }"
               : "=r"(a) : "l"(p));
    return a;
}
__device__ __forceinline__ void cpa16(u32 dst, const void* src) {
    asm volatile("cp.async.cg.shared.global [%0], [%1], 16;"
                 :: "r"(dst), "l"(src) : "memory");
}
#define CP_COMMIT() asm volatile("cp.async.commit_group;" ::: "memory")
#define CP_WAIT(n)  asm volatile("cp.async.wait_group %0;" :: "n"(n) : "memory")

typedef wmma::fragment<wmma::matrix_a, 16, 16, 16, __nv_bfloat16, wmma::row_major> FragA;
typedef wmma::fragment<wmma::matrix_b, 16, 16, 16, __nv_bfloat16, wmma::col_major> FragB;
typedef wmma::fragment<wmma::matrix_b, 16, 16, 16, __nv_bfloat16, wmma::row_major> FragBr;
typedef wmma::fragment<wmma::accumulator, 16, 16, 16, float> FragC;

// shared 3-product hi/lo microkernel: warp tile 32x64, K=128, ldm 136.
// BROW=false: B stored [n][k] (col_major frag); BROW=true: B stored [k][n].
template<bool BROW, class FB>
__device__ __forceinline__ void mma3(const __nv_bfloat16* pAh, const __nv_bfloat16* pAl,
                                     const __nv_bfloat16* pBh, const __nv_bfloat16* pBl,
                                     FragC (&acc)[2][4])
{
#pragma unroll
    for (int kt = 0; kt < 8; kt++) {
        int k0 = kt * 16;
        FragA ah[2], al[2];
        FB bh[4], bl[4];
#pragma unroll
        for (int i = 0; i < 2; i++) {
            wmma::load_matrix_sync(ah[i], pAh + (16 * i) * 136 + k0, 136);
            wmma::load_matrix_sync(al[i], pAl + (16 * i) * 136 + k0, 136);
        }
#pragma unroll
        for (int j = 0; j < 4; j++) {
            int o = BROW ? (k0 * 136 + 16 * j) : ((16 * j) * 136 + k0);
            wmma::load_matrix_sync(bh[j], pBh + o, 136);
            wmma::load_matrix_sync(bl[j], pBl + o, 136);
        }
#pragma unroll
        for (int i = 0; i < 2; i++)
#pragma unroll
            for (int j = 0; j < 4; j++) {
                wmma::mma_sync(acc[i][j], ah[i], bh[j], acc[i][j]);
                wmma::mma_sync(acc[i][j], ah[i], bl[j], acc[i][j]);
                wmma::mma_sync(acc[i][j], al[i], bh[j], acc[i][j]);
            }
    }
}

// ============ prep: x -> channel-last bf16 hi/lo ============
__global__ __launch_bounds__(256)
void prep_x_kernel(const float* __restrict__ x)
{
    __shared__ float sb[64][130];
    int y = blockIdx.x, img = blockIdx.y, tid = threadIdx.x;
    for (int ch = 0; ch < 2; ch++) {
        for (int idx = tid; idx < 64 * 128; idx += 256) {
            int cl = idx >> 7, xp = idx & 127;
            sb[cl][xp] = x[((size_t)img * 128 + ch * 64 + cl) * HWs + y * 128 + xp];
        }
        __syncthreads();
        for (int idx = tid; idx < 64 * 128; idx += 256) {
            int px = idx >> 6, cl = idx & 63;
            __nv_bfloat16 h, l;
            bsplit(sb[cl][px], h, l);
            size_t o = (((size_t)img * 128 + y) * 128 + px) * 128 + ch * 64 + cl;
            g_xh[o] = h; g_xl[o] = l;
        }
        __syncthreads();
    }
}

// ============ prep: weights ============
__global__ void prep_w3_kernel(const float* __restrict__ wo)
{
    int i = blockIdx.x * 256 + threadIdx.x;
    if (i >= 9 * 128 * 128) return;
    int tap = i / 16384, r = i % 16384, oc = r >> 7, ic = r & 127;
    __nv_bfloat16 h, l;
    bsplit(wo[((size_t)oc * 128 + ic) * 9 + tap], h, l);
    size_t o = ((size_t)tap * 128 + oc) * 128 + ic;
    g_w3h[o] = h; g_w3l[o] = l;
}
__global__ void prep_w1_kernel(const float* __restrict__ wq,
                               const float* __restrict__ wk,
                               const float* __restrict__ wv)
{
    int i = blockIdx.x * 256 + threadIdx.x;
    if (i >= 3 * 16384) return;
    int o = i / 16384, r = i % 16384;
    const float* w = (o == 0) ? wq : (o == 1) ? wk : wv;
    __nv_bfloat16 h, l;
    bsplit(w[r], h, l);
    g_w1h[i] = h; g_w1l[i] = l;
}

// ============ conv1x1 fused q/k/v ============
__global__ __launch_bounds__(256)
void conv1_fused_kernel(const float* __restrict__ bq, const float* __restrict__ bk,
                        const float* __restrict__ bv)
{
    extern __shared__ __align__(16) char smem[];
    u32 sb = smem_u32(smem);
    const u32 AH = 0, AL = 34816;
    const u32 BB0 = 69632, BB1 = 139264;

    int y = blockIdx.x, img = blockIdx.y;
    int tid = threadIdx.x, wid = tid >> 5;
    int px0 = (wid & 3) * 32, oc0 = (wid >> 2) * 64;

    {
        size_t base = (((size_t)img * 128 + y) * 128) * 128;
        for (int idx = tid; idx < 2048; idx += 256) {
            int row = idx >> 4, k8 = (idx & 15) << 3;
            u32 d = (u32)(row * 136 + k8) * 2;
            cpa16(sb + AH + d, g_xh + base + row * 128 + k8);
            cpa16(sb + AL + d, g_xl + base + row * 128 + k8);
            cpa16(sb + BB0 + d,         g_w1h + row * 128 + k8);
            cpa16(sb + BB0 + 34816 + d, g_w1l + row * 128 + k8);
        }
        CP_COMMIT();
    }

    int b = img >> 3, t = img & 7;
    int pq = tid & 31, og = tid >> 5;

    for (int o = 0; o < 3; o++) {
        CP_WAIT(0);
        __syncthreads();
        u32 BB = (o & 1) ? BB1 : BB0;
        if (o < 2) {
            u32 BBn = ((o + 1) & 1) ? BB1 : BB0;
            const __nv_bfloat16* wh = g_w1h + (size_t)(o + 1) * 16384;
            const __nv_bfloat16* wl = g_w1l + (size_t)(o + 1) * 16384;
            for (int idx = tid; idx < 2048; idx += 256) {
                int row = idx >> 4, k8 = (idx & 15) << 3;
                u32 d = (u32)(row * 136 + k8) * 2;
                cpa16(sb + BBn + d,         wh + row * 128 + k8);
                cpa16(sb + BBn + 34816 + d, wl + row * 128 + k8);
            }
            CP_COMMIT();
        }

        FragC acc[2][4];
#pragma unroll
        for (int i = 0; i < 2; i++)
#pragma unroll
            for (int j = 0; j < 4; j++) wmma::fill_fragment(acc[i][j], 0.f);

        mma3<false, FragB>((const __nv_bfloat16*)(smem + AH) + px0 * 136,
                           (const __nv_bfloat16*)(smem + AL) + px0 * 136,
                           (const __nv_bfloat16*)(smem + BB) + oc0 * 136,
                           (const __nv_bfloat16*)(smem + BB + 34816) + oc0 * 136, acc);
        __syncthreads();

        float* Cs = (float*)(smem + BB);
#pragma unroll
        for (int i = 0; i < 2; i++)
#pragma unroll
            for (int j = 0; j < 4; j++)
                wmma::store_matrix_sync(&Cs[(px0 + 16 * i) * 132 + oc0 + 16 * j],
                                        acc[i][j], 132, wmma::mem_row_major);
        __syncthreads();

        const float* bias = (o == 0) ? bq : (o == 1) ? bk : bv;
        float* dstf = (o == 0) ? g_qw : (o == 1) ? g_kw : g_vw;
        __nv_bfloat16* dsth = (o == 0) ? g_qh : (o == 1) ? g_kh : g_vh;
        __nv_bfloat16* dstl = (o == 0) ? g_ql : (o == 1) ? g_kl : g_vl;

        for (int j = 0; j < 16; j++) {
            int oc = og * 16 + j;
            int s = oc >> 5, lph = 7 - s;
            int phm = (1 << lph) - 1;
            int n_s = 8 << (2 * s), d_s = 524288 >> (2 * s);
            int oy = y >> lph, py = y & phm;
            int tokb = ((t << s) + oy) << s;
            int eb = (((oc & 31) << lph) + py) << lph;
            float bv2 = bias[oc];
            size_t base2 = ((size_t)(b * n_s + tokb)) * d_s + eb;
#pragma unroll
            for (int k2 = 0; k2 < 4; k2++) {
                int px = pq + 32 * k2;
                int ox = px >> lph, pxm = px & phm;
                float v = Cs[px * 132 + oc] + bv2;
                size_t a = base2 + (size_t)ox * d_s + pxm;
                if (s < 2) {
                    dstf[(size_t)s * 8388608 + a] = v;
                } else {
                    __nv_bfloat16 h, l;
                    bsplit(v, h, l);
                    dsth[(size_t)(s - 2) * 8388608 + a] = h;
                    dstl[(size_t)(s - 2) * 8388608 + a] = l;
                }
            }
        }
        __syncthreads();
    }
}

// ============ scale-0 scores (n=8, d=524288, fp32) ============
__global__ __launch_bounds__(256)
void scores0_kernel()
{
    __shared__ float Qs[8][516];
    __shared__ float Ks[8][516];
    __shared__ float sred[256];
    int z = blockIdx.x, b = blockIdx.y, tid = threadIdx.x;
    const int d = 524288;

    const float* qb = g_qw + ((size_t)(b * 8)) * d + z * 512;
    const float* kb = g_kw + ((size_t)(b * 8)) * d + z * 512;
    for (int idx = tid; idx < 1024; idx += 256) {
        int r = idx >> 7, c4 = (idx & 127) * 4;
        *(float4*)&Qs[r][c4] = *(const float4*)(qb + (size_t)r * d + c4);
        *(float4*)&Ks[r][c4] = *(const float4*)(kb + (size_t)r * d + c4);
    }
    __syncthreads();

    int rm = tid & 63, r = rm >> 3, m = rm & 7, kg = tid >> 6;
    ull acc = 0ull;
    int kb0 = kg * 128;
#pragma unroll
    for (int kk2 = 0; kk2 < 64; kk2++)
        ffma2(acc, *(const ull*)&Qs[r][kb0 + 2 * kk2], *(const ull*)&Ks[m][kb0 + 2 * kk2]);
    sred[tid] = hsum2(acc);
    __syncthreads();
    if (tid < 64)
        g_part[(size_t)(z * NBm + b) * 64 + tid] =
            sred[tid] + sred[tid + 64] + sred[tid + 128] + sred[tid + 192];
}

// ============ scale-1 scores (scalar, split-k) ============
template<int BN, int TN>
__global__ __launch_bounds__(256)
void scores2_kernel(int n, int d, long long off_ll, int tilesM, int dchunk)
{
    __shared__ float Qs[BN][68];
    __shared__ float Ks[BN][68];
    size_t off = (size_t)off_ll;
    int b = blockIdx.y, z = blockIdx.z;
    int tn = blockIdx.x / tilesM, tm = blockIdx.x - tn * tilesM;
    int n0 = tn * BN, m0 = tm * BN;
    int tx = threadIdx.x, ty = threadIdx.y, tid = ty * 16 + tx;

    ull acc[TN][TN];
#pragma unroll
    for (int i = 0; i < TN; i++)
#pragma unroll
        for (int j = 0; j < TN; j++) acc[i][j] = 0ull;

    const float* qb = g_qw + off + ((size_t)(b * n + n0)) * d;
    const float* kb = g_kw + off + ((size_t)(b * n + m0)) * d;
    int r0 = ty * TN;
    int k0s = z * dchunk;

    for (int k0 = k0s; k0 < k0s + dchunk; k0 += 64) {
        for (int idx = tid; idx < BN * 16; idx += 256) {
            int r = idx >> 4, c4 = (idx & 15) * 4;
            *(float4*)&Qs[r][c4] = *(const float4*)(qb + (size_t)r * d + k0 + c4);
            *(float4*)&Ks[r][c4] = *(const float4*)(kb + (size_t)r * d + k0 + c4);
        }
        __syncthreads();
#pragma unroll
        for (int kk2 = 0; kk2 < 32; kk2++) {
            ull q2[TN], k2[TN];
#pragma unroll
            for (int i = 0; i < TN; i++) q2[i] = *(const ull*)&Qs[r0 + i][2 * kk2];
#pragma unroll
            for (int j = 0; j < TN; j++) k2[j] = *(const ull*)&Ks[tx + 16 * j][2 * kk2];
#pragma unroll
            for (int i = 0; i < TN; i++)
#pragma unroll
                for (int j = 0; j < TN; j++) ffma2(acc[i][j], q2[i], k2[j]);
        }
        __syncthreads();
    }

    size_t base = ((size_t)(z * NBm + b)) * n * n;
#pragma unroll
    for (int i = 0; i < TN; i++)
#pragma unroll
        for (int j = 0; j < TN; j++)
            g_part[base + (size_t)(n0 + r0 + i) * n + (m0 + tx + 16 * j)] =
                hsum2(acc[i][j]);
}

// ============ WMMA scores (scales 2,3) ============
__global__ __launch_bounds__(256)
void scores_wmma_kernel(int n, int d, long long offb_ll, int tilesM, int dchunk)
{
    extern __shared__ __align__(16) char smem[];
    u32 sb = smem_u32(smem);
    const u32 QH = 0, QL = 34816, KH = 69632, KL = 104448;
    size_t offb = (size_t)offb_ll;
    int b = blockIdx.y, z = blockIdx.z;
    int tn = blockIdx.x / tilesM, tm = blockIdx.x - tn * tilesM;
    int n0 = tn * 128, m0 = tm * 128;
    int tid = threadIdx.x, wid = tid >> 5;
    int px0 = (wid & 3) * 32, oc0 = (wid >> 2) * 64;

    const __nv_bfloat16* qh = g_qh + offb + ((size_t)(b * n + n0)) * d;
    const __nv_bfloat16* ql = g_ql + offb + ((size_t)(b * n + n0)) * d;
    const __nv_bfloat16* kh = g_kh + offb + ((size_t)(b * n + m0)) * d;
    const __nv_bfloat16* kl = g_kl + offb + ((size_t)(b * n + m0)) * d;

    FragC acc[2][4];
#pragma unroll
    for (int i = 0; i < 2; i++)
#pragma unroll
        for (int j = 0; j < 4; j++) wmma::fill_fragment(acc[i][j], 0.f);

    int k0s = z * dchunk;
    for (int k0 = k0s; k0 < k0s + dchunk; k0 += 128) {
        for (int idx = tid; idx < 2048; idx += 256) {
            int r = idx >> 4, k8 = (idx & 15) << 3;
            u32 dd = (u32)(r * 136 + k8) * 2;
            size_t go = (size_t)r * d + k0 + k8;
            cpa16(sb + QH + dd, qh + go);
            cpa16(sb + QL + dd, ql + go);
            cpa16(sb + KH + dd, kh + go);
            cpa16(sb + KL + dd, kl + go);
        }
        CP_COMMIT(); CP_WAIT(0);
        __syncthreads();
        mma3<false, FragB>((const __nv_bfloat16*)(smem + QH) + px0 * 136,
                           (const __nv_bfloat16*)(smem + QL) + px0 * 136,
                           (const __nv_bfloat16*)(smem + KH) + oc0 * 136,
                           (const __nv_bfloat16*)(smem + KL) + oc0 * 136, acc);
        __syncthreads();
    }

    size_t base = ((size_t)(z * NBm + b)) * n * n;
#pragma unroll
    for (int i = 0; i < 2; i++)
#pragma unroll
        for (int j = 0; j < 4; j++)
            wmma::store_matrix_sync(
                g_part + base + (size_t)(n0 + px0 + 16 * i) * n + m0 + oc0 + 16 * j,
                acc[i][j], n, wmma::mem_row_major);
}

// ============ reduce + softmax (+ optional bf16 attn output) ============
__global__ __launch_bounds__(256)
void softmax_kernel(int n, int nsplit, float isd, int wbf)
{
    __shared__ float sbuf[512];
    __shared__ float red[256];
    int row = blockIdx.x, b = blockIdx.y, tid = threadIdx.x;

    if (n <= 32) {
        int m = tid % n, zi = tid / n, tpm = 256 / n;
        float s = 0.f;
        for (int z = zi; z < nsplit; z += tpm)
            s += g_part[((size_t)(z * NBm + b) * n + row) * n + m];
        red[tid] = s;
        __syncthreads();
        if (tid < n) {
            float t = 0.f;
            for (int j = 0; j < tpm; j++) t += red[tid + j * n];
            sbuf[tid] = t * isd;
        }
    } else {
        for (int m = tid; m < n; m += 256) {
            float s = 0.f;
            for (int z = 0; z < nsplit; z++)
                s += g_part[((size_t)(z * NBm + b) * n + row) * n + m];
            sbuf[m] = s * isd;
        }
    }
    __syncthreads();

    float lm = -1e30f;
    for (int m = tid; m < n; m += 256) lm = fmaxf(lm, sbuf[m]);
    red[tid] = lm;
    __syncthreads();
    for (int s = 128; s > 0; s >>= 1) {
        if (tid < s) red[tid] = fmaxf(red[tid], red[tid + s]);
        __syncthreads();
    }
    float mx = red[0];
    __syncthreads();
    float ls = 0.f;
    for (int m = tid; m < n; m += 256) {
        float e = __expf(sbuf[m] - mx);
        sbuf[m] = e; ls += e;
    }
    red[tid] = ls;
    __syncthreads();
    for (int s = 128; s > 0; s >>= 1) {
        if (tid < s) red[tid] += red[tid + s];
        __syncthreads();
    }
    float inv = 1.0f / red[0];
    for (int m = tid; m < n; m += 256) {
        float p = sbuf[m] * inv;
        size_t o = ((size_t)b * n + row) * n + m;
        if (wbf) {
            __nv_bfloat16 h, l;
            bsplit(p, h, l);
            g_ath[o] = h; g_atl[o] = l;
        } else {
            g_attn[o] = p;
        }
    }
}

// ============ scalar AV (scales 0,1) ============
template<int BN, int TN>
__global__ __launch_bounds__(256)
void av2_kernel(int n, int d, long long off_ll)
{
    __shared__ float As[BN][34];
    __shared__ float Vs[32][66];
    size_t off = (size_t)off_ll;
    int b = blockIdx.z, n0 = blockIdx.y * BN, e0 = blockIdx.x * 64;
    int tx = threadIdx.x, ty = threadIdx.y, tid = ty * 16 + tx;

    ull acc[TN][2];
#pragma unroll
    for (int i = 0; i < TN; i++) { acc[i][0] = 0ull; acc[i][1] = 0ull; }
    int r0 = ty * TN;

    const float* vb = g_vw + off + e0;

    for (int m0 = 0; m0 < n; m0 += 32) {
        for (int idx = tid; idx < BN * 8; idx += 256) {
            int r = idx >> 3, c4 = (idx & 7) * 4;
            float4 v = (m0 + c4 < n)
                ? *(const float4*)(g_attn + ((size_t)(b * n + n0 + r)) * n + m0 + c4)
                : make_float4(0.f, 0.f, 0.f, 0.f);
            As[r][c4] = v.x; As[r][c4 + 1] = v.y; As[r][c4 + 2] = v.z; As[r][c4 + 3] = v.w;
        }
        for (int idx = tid; idx < 512; idx += 256) {
            int mm = idx >> 4, e4 = (idx & 15) * 4;
            float4 v = (m0 + mm < n)
                ? *(const float4*)(vb + ((size_t)(b * n + m0 + mm)) * d + e4)
                : make_float4(0.f, 0.f, 0.f, 0.f);
            Vs[mm][e4] = v.x; Vs[mm][e4 + 1] = v.y; Vs[mm][e4 + 2] = v.z; Vs[mm][e4 + 3] = v.w;
        }
        __syncthreads();
#pragma unroll
        for (int kk = 0; kk < 32; kk++) {
            ull v2a = *(const ull*)&Vs[kk][2 * tx];
            ull v2b = *(const ull*)&Vs[kk][2 * tx + 32];
#pragma unroll
            for (int i = 0; i < TN; i++) {
                ull a2 = pack2(As[r0 + i][kk]);
                ffma2(acc[i][0], a2, v2a);
                ffma2(acc[i][1], a2, v2b);
            }
        }
        __syncthreads();
    }

    float* ob = g_ow + off;
#pragma unroll
    for (int i = 0; i < TN; i++) {
        size_t rb = ((size_t)(b * n + n0 + r0 + i)) * d + e0;
        *(float2*)(ob + rb + 2 * tx)      = *reinterpret_cast<float2*>(&acc[i][0]);
        *(float2*)(ob + rb + 2 * tx + 32) = *reinterpret_cast<float2*>(&acc[i][1]);
    }
}

// ============ WMMA AV (scales 2,3) ============
__global__ __launch_bounds__(256)
void av_wmma_kernel(int n, int d, long long offb_ll, long long off32_ll)
{
    extern __shared__ __align__(16) char smem[];
    u32 sb = smem_u32(smem);
    const u32 AH = 0, AL = 34816, VH = 69632, VL = 104448;
    size_t offb = (size_t)offb_ll, off32 = (size_t)off32_ll;
    int b = blockIdx.z, n0 = blockIdx.y * 128, e0 = blockIdx.x * 128;
    int tid = threadIdx.x, wid = tid >> 5;
    int px0 = (wid & 3) * 32, oc0 = (wid >> 2) * 64;

    FragC acc[2][4];
#pragma unroll
    for (int i = 0; i < 2; i++)
#pragma unroll
        for (int j = 0; j < 4; j++) wmma::fill_fragment(acc[i][j], 0.f);

    for (int m0 = 0; m0 < n; m0 += 128) {
        for (int idx = tid; idx < 2048; idx += 256) {
            int r = idx >> 4, k8 = (idx & 15) << 3;
            u32 dd = (u32)(r * 136 + k8) * 2;
            size_t ao = ((size_t)(b * n + n0 + r)) * n + m0 + k8;
            size_t vo = offb + ((size_t)(b * n + m0 + r)) * d + e0 + k8;
            cpa16(sb + AH + dd, g_ath + ao);
            cpa16(sb + AL + dd, g_atl + ao);
            cpa16(sb + VH + dd, g_vh + vo);
            cpa16(sb + VL + dd, g_vl + vo);
        }
        CP_COMMIT(); CP_WAIT(0);
        __syncthreads();
        mma3<true, FragBr>((const __nv_bfloat16*)(smem + AH) + px0 * 136,
                           (const __nv_bfloat16*)(smem + AL) + px0 * 136,
                           (const __nv_bfloat16*)(smem + VH) + oc0,
                           (const __nv_bfloat16*)(smem + VL) + oc0, acc);
        __syncthreads();
    }

#pragma unroll
    for (int i = 0; i < 2; i++)
#pragma unroll
        for (int j = 0; j < 4; j++)
            wmma::store_matrix_sync(
                g_ow + off32 + ((size_t)(b * n + n0 + px0 + 16 * i)) * d + e0 + oc0 + 16 * j,
                acc[i][j], d, wmma::mem_row_major);
}

// ============ unpack windowed -> channel-last bf16 hi/lo ============
__global__ __launch_bounds__(256)
void unpack2_kernel()
{
    __shared__ float sbm[64][130];
    int y = blockIdx.x, img = blockIdx.y, tid = threadIdx.x;
    int b = img >> 3, t = img & 7;
    for (int ch = 0; ch < 2; ch++) {
        for (int idx = tid; idx < 64 * 128; idx += 256) {
            int cl = idx >> 7, xp = idx & 127;
            int c = ch * 64 + cl;
            int s = c >> 5, lph = 7 - s;
            int phm = (1 << lph) - 1;
            int n_s = 8 << (2 * s), d_s = 524288 >> (2 * s);
            int oy = y >> lph, py = y & phm;
            int ox = xp >> lph, pxm = xp & phm;
            int tok = ((((t << s) + oy) << s) + ox);
            int e = ((((c & 31) << lph) + py) << lph) + pxm;
            sbm[cl][xp] = g_ow[(size_t)s * 8388608 + ((size_t)(b * n_s + tok)) * d_s + e];
        }
        __syncthreads();
        for (int idx = tid; idx < 64 * 128; idx += 256) {
            int px = idx >> 6, cl = idx & 63;
            __nv_bfloat16 h, l;
            bsplit(sbm[cl][px], h, l);
            size_t o = (((size_t)img * 128 + y) * 128 + px) * 128 + ch * 64 + cl;
            g_ah[o] = h; g_al[o] = l;
        }
        __syncthreads();
    }
}

// ============ conv3x3 via WMMA + cp.async tap pipeline ============
__global__ __launch_bounds__(256)
void conv3_pipe_kernel(const float* __restrict__ bias, float* __restrict__ out)
{
    extern __shared__ __align__(16) char smem[];
    u32 sb = smem_u32(smem);
    const u32 AH = 0, AL = 35360;
    const u32 BB0 = 70720, BB1 = 140352;

    int y = blockIdx.x, img = blockIdx.y;
    int tid = threadIdx.x, wid = tid >> 5;
    int px0 = (wid & 3) * 32, oc0 = (wid >> 2) * 64;

    FragC acc[2][4];
#pragma unroll
    for (int i = 0; i < 2; i++)
#pragma unroll
        for (int j = 0; j < 4; j++) wmma::fill_fragment(acc[i][j], 0.f);

    for (int idx = tid; idx < 2048; idx += 256) {
        int row = idx >> 4, k8 = (idx & 15) << 3;
        u32 d = (u32)(row * 136 + k8) * 2;
        cpa16(sb + BB0 + d,         g_w3h + row * 128 + k8);
        cpa16(sb + BB0 + 34816 + d, g_w3l + row * 128 + k8);
    }
    CP_COMMIT();

    for (int tp = 0; tp < 9; tp++) {
        int ky = tp / 3, kx = tp - ky * 3;
        CP_WAIT(0);
        __syncthreads();
        if (kx == 0) {
            int yy = y + ky - 1;
            bool yok = (yy >= 0 && yy < 128);
            size_t abase = (((size_t)img * 128 + (yok ? yy : 0)) * 128) * 128;
            for (int idx = tid; idx < 2080; idx += 256) {
                int i = idx >> 4, k8 = (idx & 15) << 3;
                int px = i - 1;
                u32 d = (u32)(i * 136 + k8) * 2;
                if (yok && px >= 0 && px < 128) {
                    size_t o = abase + (size_t)px * 128 + k8;
                    cpa16(sb + AH + d, g_ah + o);
                    cpa16(sb + AL + d, g_al + o);
                } else {
                    uint4 z = make_uint4(0, 0, 0, 0);
                    *(uint4*)(smem + AH + d) = z;
                    *(uint4*)(smem + AL + d) = z;
                }
            }
            CP_COMMIT();
        }
        if (tp < 8) {
            u32 BBn = ((tp + 1) & 1) ? BB1 : BB0;
            const __nv_bfloat16* wh = g_w3h + (size_t)(tp + 1) * 16384;
            const __nv_bfloat16* wl = g_w3l + (size_t)(tp + 1) * 16384;
            for (int idx = tid; idx < 2048; idx += 256) {
                int row = idx >> 4, k8 = (idx & 15) << 3;
                u32 d = (u32)(row * 136 + k8) * 2;
                cpa16(sb + BBn + d,         wh + row * 128 + k8);
                cpa16(sb + BBn + 34816 + d, wl + row * 128 + k8);
            }
            CP_COMMIT();
        }
        if (kx == 0) {
            if (tp < 8) { CP_WAIT(1); } else { CP_WAIT(0); }
            __syncthreads();
        }

        u32 BB = (tp & 1) ? BB1 : BB0;
        mma3<false, FragB>((const __nv_bfloat16*)(smem + AH) + (px0 + kx) * 136,
                           (const __nv_bfloat16*)(smem + AL) + (px0 + kx) * 136,
                           (const __nv_bfloat16*)(smem + BB) + oc0 * 136,
                           (const __nv_bfloat16*)(smem + BB + 34816) + oc0 * 136, acc);
        __syncthreads();
    }

    float* Cs = (float*)(smem + BB0);
#pragma unroll
    for (int i = 0; i < 2; i++)
#pragma unroll
        for (int j = 0; j < 4; j++)
            wmma::store_matrix_sync(&Cs[(px0 + 16 * i) * 132 + oc0 + 16 * j],
                                    acc[i][j], 132, wmma::mem_row_major);
    __syncthreads();

    for (int idx = tid; idx < 16384; idx += 256) {
        int px = idx & 127, oc = idx >> 7;
        float v = Cs[px * 132 + oc] + bias[oc];
        out[((size_t)img * 128 + oc) * HWs + (size_t)y * 128 + px] = fmaxf(v, 0.f);
    }
}

// ============ launch ============
extern "C" void kernel_launch(void* const* d_in, const int* in_sizes, int n_in,
                              void* d_out, int out_size)
{
    const float* x  = (const float*)d_in[0];
    const float* wq = (const float*)d_in[1];
    const float* bq = (const float*)d_in[2];
    const float* wk = (const float*)d_in[3];
    const float* bk = (const float*)d_in[4];
    const float* wv = (const float*)d_in[5];
    const float* bv = (const float*)d_in[6];
    const float* wo = (const float*)d_in[7];
    const float* bo = (const float*)d_in[8];
    float* out = (float*)d_out;

    const int smem1 = 208896, smem3 = 209984, smemW = 139264;
    cudaFuncSetAttribute(conv1_fused_kernel,
                         cudaFuncAttributeMaxDynamicSharedMemorySize, smem1);
    cudaFuncSetAttribute(conv3_pipe_kernel,
                         cudaFuncAttributeMaxDynamicSharedMemorySize, smem3);
    cudaFuncSetAttribute(scores_wmma_kernel,
                         cudaFuncAttributeMaxDynamicSharedMemorySize, smemW);
    cudaFuncSetAttribute(av_wmma_kernel,
                         cudaFuncAttributeMaxDynamicSharedMemorySize, smemW);

    dim3 blk(16, 16);

    prep_w3_kernel<<<(9 * 128 * 128 + 255) / 256, 256>>>(wo);
    prep_w1_kernel<<<(3 * 16384 + 255) / 256, 256>>>(wq, wk, wv);
    prep_x_kernel<<<dim3(Hd, BT), 256>>>(x);
    conv1_fused_kernel<<<dim3(Hd, BT), 256, smem1>>>(bq, bk, bv);

    // scale 0: n=8, d=524288 (scalar fp32)
    {
        float isd = 1.0f / sqrtf(524288.f);
        scores0_kernel<<<dim3(1024, NBm), 256>>>();
        softmax_kernel<<<dim3(8, NBm), 256>>>(8, 1024, isd, 0);
        av2_kernel<8, 1><<<dim3(524288 / 64, 1, NBm), blk>>>(8, 524288, 0LL);
    }
    // scale 1: n=32, d=131072 (scalar fp32)
    {
        float isd = 1.0f / sqrtf(131072.f);
        scores2_kernel<32, 2><<<dim3(1, NBm, 256), blk>>>(32, 131072, 8388608LL, 1, 512);
        softmax_kernel<<<dim3(32, NBm), 256>>>(32, 256, isd, 0);
        av2_kernel<32, 2><<<dim3(131072 / 64, 1, NBm), blk>>>(32, 131072, 8388608LL);
    }
    // scale 2: n=128, d=32768 (WMMA)
    {
        float isd = 1.0f / sqrtf(32768.f);
        scores_wmma_kernel<<<dim3(1, NBm, 128), 256, smemW>>>(128, 32768, 0LL, 1, 256);
        softmax_kernel<<<dim3(128, NBm), 256>>>(128, 128, isd, 1);
        av_wmma_kernel<<<dim3(256, 1, NBm), 256, smemW>>>(128, 32768, 0LL, 2LL * 8388608);
    }
    // scale 3: n=512, d=8192 (WMMA)
    {
        float isd = 1.0f / sqrtf(8192.f);
        scores_wmma_kernel<<<dim3(16, NBm, 8), 256, smemW>>>(512, 8192, 8388608LL, 4, 1024);
        softmax_kernel<<<dim3(512, NBm), 256>>>(512, 8, isd, 1);
        av_wmma_kernel<<<dim3(64, 4, NBm), 256, smemW>>>(512, 8192, 8388608LL, 3LL * 8388608);
    }

    unpack2_kernel<<<dim3(Hd, BT), 256>>>();
    conv3_pipe_kernel<<<dim3(Hd, BT), 256, smem3>>>(bo, out);

    (void)in_sizes; (void)n_in; (void)out_size;
}

// round 9
// speedup vs baseline: 2.9300x; 1.0274x over previous
#include <cuda_runtime.h>
#include <cuda_bf16.h>
#include <mma.h>
#include <math.h>

using namespace nvcuda;

typedef unsigned long long ull;
typedef unsigned int u32;

#define Cc 128
#define Hd 128
#define Wd 128
#define HWs 16384
#define BT 16
#define NBm 2

// ---------------- device scratch ----------------
__device__ float g_qw[(size_t)2 * 8388608];   // scales 0,1 fp32
__device__ float g_kw[(size_t)2 * 8388608];
__device__ float g_vw[(size_t)2 * 8388608];
__device__ float g_ow[(size_t)4 * 8388608];
__device__ float g_c1[(size_t)3 * 16 * 16384 * 128];   // conv1 dense out
__device__ float g_part[(size_t)1 << 24];
__device__ float g_attn[(size_t)NBm * 512 * 512];
__device__ __nv_bfloat16 g_ath[(size_t)NBm * 512 * 512];
__device__ __nv_bfloat16 g_atl[(size_t)NBm * 512 * 512];
__device__ __nv_bfloat16 g_qh[(size_t)2 * 8388608];   // scales 2,3 bf16 hi/lo
__device__ __nv_bfloat16 g_ql[(size_t)2 * 8388608];
__device__ __nv_bfloat16 g_kh[(size_t)2 * 8388608];
__device__ __nv_bfloat16 g_kl[(size_t)2 * 8388608];
__device__ __nv_bfloat16 g_vh[(size_t)2 * 8388608];
__device__ __nv_bfloat16 g_vl[(size_t)2 * 8388608];
__device__ __nv_bfloat16 g_xh[(size_t)33554432];
__device__ __nv_bfloat16 g_xl[(size_t)33554432];
__device__ __nv_bfloat16 g_ah[(size_t)33554432];
__device__ __nv_bfloat16 g_al[(size_t)33554432];
__device__ __nv_bfloat16 g_w3h[9 * 128 * 128];
__device__ __nv_bfloat16 g_w3l[9 * 128 * 128];
__device__ __nv_bfloat16 g_w1h[3 * 128 * 128];
__device__ __nv_bfloat16 g_w1l[3 * 128 * 128];

// ---------------- helpers ----------------
__device__ __forceinline__ void ffma2(ull& d, ull a, ull b) {
    asm("fma.rn.f32x2 %0, %1, %2, %0;" : "+l"(d) : "l"(a), "l"(b));
}
__device__ __forceinline__ float hsum2(ull v) {
    float2 f = *reinterpret_cast<float2*>(&v);
    return f.x + f.y;
}
__device__ __forceinline__ ull pack2(float a) {
    ull r; asm("mov.b64 %0,{%1,%1};" : "=l"(r) : "f"(a)); return r;
}
__device__ __forceinline__ void bsplit(float v, __nv_bfloat16& h, __nv_bfloat16& l) {
    h = __float2bfloat16(v);
    l = __float2bfloat16(v - __bfloat162float(h));
}
__device__ __forceinline__ u32 smem_u32(const void* p) {
    u32 a; asm("{ .reg .u64 t; cvta.to.shared.u64 t, %1; cvt.u32.u64 %0, t; }"
               : "=r"(a) : "l"(p));
    return a;
}
__device__ __forceinline__ void cpa16(u32 dst, const void* src) {
    asm volatile("cp.async.cg.shared.global [%0], [%1], 16;"
                 :: "r"(dst), "l"(src) : "memory");
}
#define CP_COMMIT() asm volatile("cp.async.commit_group;" ::: "memory")
#define CP_WAIT(n)  asm volatile("cp.async.wait_group %0;" :: "n"(n) : "memory")

typedef wmma::fragment<wmma::matrix_a, 16, 16, 16, __nv_bfloat16, wmma::row_major> FragA;
typedef wmma::fragment<wmma::matrix_b, 16, 16, 16, __nv_bfloat16, wmma::col_major> FragB;
typedef wmma::fragment<wmma::matrix_b, 16, 16, 16, __nv_bfloat16, wmma::row_major> FragBr;
typedef wmma::fragment<wmma::accumulator, 16, 16, 16, float> FragC;

// 3-product hi/lo microkernel: warp tile 32x64, K=128, ldm 136.
template<bool BROW, class FB>
__device__ __forceinline__ void mma3(const __nv_bfloat16* pAh, const __nv_bfloat16* pAl,
                                     const __nv_bfloat16* pBh, const __nv_bfloat16* pBl,
                                     FragC (&acc)[2][4])
{
#pragma unroll
    for (int kt = 0; kt < 8; kt++) {
        int k0 = kt * 16;
        FragA ah[2], al[2];
        FB bh[4], bl[4];
#pragma unroll
        for (int i = 0; i < 2; i++) {
            wmma::load_matrix_sync(ah[i], pAh + (16 * i) * 136 + k0, 136);
            wmma::load_matrix_sync(al[i], pAl + (16 * i) * 136 + k0, 136);
        }
#pragma unroll
        for (int j = 0; j < 4; j++) {
            int o = BROW ? (k0 * 136 + 16 * j) : ((16 * j) * 136 + k0);
            wmma::load_matrix_sync(bh[j], pBh + o, 136);
            wmma::load_matrix_sync(bl[j], pBl + o, 136);
        }
#pragma unroll
        for (int i = 0; i < 2; i++)
#pragma unroll
            for (int j = 0; j < 4; j++) {
                wmma::mma_sync(acc[i][j], ah[i], bh[j], acc[i][j]);
                wmma::mma_sync(acc[i][j], ah[i], bl[j], acc[i][j]);
                wmma::mma_sync(acc[i][j], al[i], bh[j], acc[i][j]);
            }
    }
}

// ============ prep: x -> channel-last bf16 hi/lo ============
__global__ __launch_bounds__(256)
void prep_x_kernel(const float* __restrict__ x)
{
    __shared__ float sb[64][130];
    int y = blockIdx.x, img = blockIdx.y, tid = threadIdx.x;
    for (int ch = 0; ch < 2; ch++) {
        for (int idx = tid; idx < 64 * 128; idx += 256) {
            int cl = idx >> 7, xp = idx & 127;
            sb[cl][xp] = x[((size_t)img * 128 + ch * 64 + cl) * HWs + y * 128 + xp];
        }
        __syncthreads();
        for (int idx = tid; idx < 64 * 128; idx += 256) {
            int px = idx >> 6, cl = idx & 63;
            __nv_bfloat16 h, l;
            bsplit(sb[cl][px], h, l);
            size_t o = (((size_t)img * 128 + y) * 128 + px) * 128 + ch * 64 + cl;
            g_xh[o] = h; g_xl[o] = l;
        }
        __syncthreads();
    }
}

// ============ prep: weights ============
__global__ void prep_w3_kernel(const float* __restrict__ wo)
{
    int i = blockIdx.x * 256 + threadIdx.x;
    if (i >= 9 * 128 * 128) return;
    int tap = i / 16384, r = i % 16384, oc = r >> 7, ic = r & 127;
    __nv_bfloat16 h, l;
    bsplit(wo[((size_t)oc * 128 + ic) * 9 + tap], h, l);
    size_t o = ((size_t)tap * 128 + oc) * 128 + ic;
    g_w3h[o] = h; g_w3l[o] = l;
}
__global__ void prep_w1_kernel(const float* __restrict__ wq,
                               const float* __restrict__ wk,
                               const float* __restrict__ wv)
{
    int i = blockIdx.x * 256 + threadIdx.x;
    if (i >= 3 * 16384) return;
    int o = i / 16384, r = i % 16384;
    const float* w = (o == 0) ? wq : (o == 1) ? wk : wv;
    __nv_bfloat16 h, l;
    bsplit(w[r], h, l);
    g_w1h[i] = h; g_w1l[i] = l;
}

// ============ conv1x1: pure GEMM -> dense fp32 (2 CTAs/SM) ============
// blockIdx.x = y*6 + z, z = o*2 + oh. block 128. smem 104448.
__global__ __launch_bounds__(128, 2)
void conv1_v3_kernel()
{
    extern __shared__ __align__(16) char smem[];
    u32 sb = smem_u32(smem);
    const u32 AH = 0, AL = 34816, BH = 69632, BL = 87040;

    int bx = blockIdx.x, img = blockIdx.y;
    int y = bx / 6, z = bx - 6 * y;
    int o = z >> 1, oh = z & 1;
    int tid = threadIdx.x, wid = tid >> 5;
    int px0 = wid * 32;

    size_t abase = (((size_t)img * 128 + y) * 128) * 128;
    for (int idx = tid; idx < 2048; idx += 128) {
        int row = idx >> 4, k8 = (idx & 15) << 3;
        u32 d = (u32)(row * 136 + k8) * 2;
        cpa16(sb + AH + d, g_xh + abase + row * 128 + k8);
        cpa16(sb + AL + d, g_xl + abase + row * 128 + k8);
    }
    const __nv_bfloat16* wh = g_w1h + (size_t)o * 16384 + oh * 8192;
    const __nv_bfloat16* wl = g_w1l + (size_t)o * 16384 + oh * 8192;
    for (int idx = tid; idx < 1024; idx += 128) {
        int row = idx >> 4, k8 = (idx & 15) << 3;
        u32 d = (u32)(row * 136 + k8) * 2;
        cpa16(sb + BH + d, wh + row * 128 + k8);
        cpa16(sb + BL + d, wl + row * 128 + k8);
    }
    CP_COMMIT(); CP_WAIT(0);
    __syncthreads();

    FragC acc[2][4];
#pragma unroll
    for (int i = 0; i < 2; i++)
#pragma unroll
        for (int j = 0; j < 4; j++) wmma::fill_fragment(acc[i][j], 0.f);

    mma3<false, FragB>((const __nv_bfloat16*)(smem + AH) + px0 * 136,
                       (const __nv_bfloat16*)(smem + AL) + px0 * 136,
                       (const __nv_bfloat16*)(smem + BH),
                       (const __nv_bfloat16*)(smem + BL), acc);

    size_t cbase = ((size_t)(o * 16 + img) * 16384 + (size_t)y * 128);
#pragma unroll
    for (int i = 0; i < 2; i++)
#pragma unroll
        for (int j = 0; j < 4; j++)
            wmma::store_matrix_sync(
                g_c1 + (cbase + px0 + 16 * i) * 128 + oh * 64 + 16 * j,
                acc[i][j], 128, wmma::mem_row_major);
}

// ============ qkv scatter: dense -> windowed (+bias, bf16 split for s>=2) ====
__global__ __launch_bounds__(256)
void qkv_scatter_kernel(const float* __restrict__ bq, const float* __restrict__ bk,
                        const float* __restrict__ bv)
{
    extern __shared__ __align__(16) char smemc[];
    float* Cs = (float*)smemc;   // [128][132]
    int y = blockIdx.x, img = blockIdx.y, tid = threadIdx.x;
    int b = img >> 3, t = img & 7;
    int pq = tid & 31, og = tid >> 5;

    for (int o = 0; o < 3; o++) {
        __syncthreads();
        const float* src = g_c1 + ((size_t)(o * 16 + img) * 16384 + (size_t)y * 128) * 128;
        for (int idx = tid; idx < 4096; idx += 256) {
            int px = idx >> 5, oc4 = (idx & 31) * 4;
            *(float4*)&Cs[px * 132 + oc4] = *(const float4*)(src + (size_t)px * 128 + oc4);
        }
        __syncthreads();

        const float* bias = (o == 0) ? bq : (o == 1) ? bk : bv;
        float* dstf = (o == 0) ? g_qw : (o == 1) ? g_kw : g_vw;
        __nv_bfloat16* dsth = (o == 0) ? g_qh : (o == 1) ? g_kh : g_vh;
        __nv_bfloat16* dstl = (o == 0) ? g_ql : (o == 1) ? g_kl : g_vl;

        for (int j = 0; j < 16; j++) {
            int oc = og * 16 + j;
            int s = oc >> 5, lph = 7 - s;
            int phm = (1 << lph) - 1;
            int n_s = 8 << (2 * s), d_s = 524288 >> (2 * s);
            int oy = y >> lph, py = y & phm;
            int tokb = ((t << s) + oy) << s;
            int eb = (((oc & 31) << lph) + py) << lph;
            float bv2 = bias[oc];
            size_t base2 = ((size_t)(b * n_s + tokb)) * d_s + eb;
#pragma unroll
            for (int k2 = 0; k2 < 4; k2++) {
                int px = pq + 32 * k2;
                int ox = px >> lph, pxm = px & phm;
                float v = Cs[px * 132 + oc] + bv2;
                size_t a = base2 + (size_t)ox * d_s + pxm;
                if (s < 2) {
                    dstf[(size_t)s * 8388608 + a] = v;
                } else {
                    __nv_bfloat16 h, l;
                    bsplit(v, h, l);
                    dsth[(size_t)(s - 2) * 8388608 + a] = h;
                    dstl[(size_t)(s - 2) * 8388608 + a] = l;
                }
            }
        }
    }
}

// ============ scale-0 scores (n=8, d=524288, fp32) ============
__global__ __launch_bounds__(256)
void scores0_kernel()
{
    __shared__ float Qs[8][516];
    __shared__ float Ks[8][516];
    __shared__ float sred[256];
    int z = blockIdx.x, b = blockIdx.y, tid = threadIdx.x;
    const int d = 524288;

    const float* qb = g_qw + ((size_t)(b * 8)) * d + z * 512;
    const float* kb = g_kw + ((size_t)(b * 8)) * d + z * 512;
    for (int idx = tid; idx < 1024; idx += 256) {
        int r = idx >> 7, c4 = (idx & 127) * 4;
        *(float4*)&Qs[r][c4] = *(const float4*)(qb + (size_t)r * d + c4);
        *(float4*)&Ks[r][c4] = *(const float4*)(kb + (size_t)r * d + c4);
    }
    __syncthreads();

    int rm = tid & 63, r = rm >> 3, m = rm & 7, kg = tid >> 6;
    ull acc = 0ull;
    int kb0 = kg * 128;
#pragma unroll
    for (int kk2 = 0; kk2 < 64; kk2++)
        ffma2(acc, *(const ull*)&Qs[r][kb0 + 2 * kk2], *(const ull*)&Ks[m][kb0 + 2 * kk2]);
    sred[tid] = hsum2(acc);
    __syncthreads();
    if (tid < 64)
        g_part[(size_t)(z * NBm + b) * 64 + tid] =
            sred[tid] + sred[tid + 64] + sred[tid + 128] + sred[tid + 192];
}

// ============ scale-1 scores (scalar, split-k) ============
template<int BN, int TN>
__global__ __launch_bounds__(256)
void scores2_kernel(int n, int d, long long off_ll, int tilesM, int dchunk)
{
    __shared__ float Qs[BN][68];
    __shared__ float Ks[BN][68];
    size_t off = (size_t)off_ll;
    int b = blockIdx.y, z = blockIdx.z;
    int tn = blockIdx.x / tilesM, tm = blockIdx.x - tn * tilesM;
    int n0 = tn * BN, m0 = tm * BN;
    int tx = threadIdx.x, ty = threadIdx.y, tid = ty * 16 + tx;

    ull acc[TN][TN];
#pragma unroll
    for (int i = 0; i < TN; i++)
#pragma unroll
        for (int j = 0; j < TN; j++) acc[i][j] = 0ull;

    const float* qb = g_qw + off + ((size_t)(b * n + n0)) * d;
    const float* kb = g_kw + off + ((size_t)(b * n + m0)) * d;
    int r0 = ty * TN;
    int k0s = z * dchunk;

    for (int k0 = k0s; k0 < k0s + dchunk; k0 += 64) {
        for (int idx = tid; idx < BN * 16; idx += 256) {
            int r = idx >> 4, c4 = (idx & 15) * 4;
            *(float4*)&Qs[r][c4] = *(const float4*)(qb + (size_t)r * d + k0 + c4);
            *(float4*)&Ks[r][c4] = *(const float4*)(kb + (size_t)r * d + k0 + c4);
        }
        __syncthreads();
#pragma unroll
        for (int kk2 = 0; kk2 < 32; kk2++) {
            ull q2[TN], k2[TN];
#pragma unroll
            for (int i = 0; i < TN; i++) q2[i] = *(const ull*)&Qs[r0 + i][2 * kk2];
#pragma unroll
            for (int j = 0; j < TN; j++) k2[j] = *(const ull*)&Ks[tx + 16 * j][2 * kk2];
#pragma unroll
            for (int i = 0; i < TN; i++)
#pragma unroll
                for (int j = 0; j < TN; j++) ffma2(acc[i][j], q2[i], k2[j]);
        }
        __syncthreads();
    }

    size_t base = ((size_t)(z * NBm + b)) * n * n;
#pragma unroll
    for (int i = 0; i < TN; i++)
#pragma unroll
        for (int j = 0; j < TN; j++)
            g_part[base + (size_t)(n0 + r0 + i) * n + (m0 + tx + 16 * j)] =
                hsum2(acc[i][j]);
}

// ============ WMMA scores (scales 2,3) ============
__global__ __launch_bounds__(256)
void scores_wmma_kernel(int n, int d, long long offb_ll, int tilesM, int dchunk)
{
    extern __shared__ __align__(16) char smem[];
    u32 sb = smem_u32(smem);
    const u32 QH = 0, QL = 34816, KH = 69632, KL = 104448;
    size_t offb = (size_t)offb_ll;
    int b = blockIdx.y, z = blockIdx.z;
    int tn = blockIdx.x / tilesM, tm = blockIdx.x - tn * tilesM;
    int n0 = tn * 128, m0 = tm * 128;
    int tid = threadIdx.x, wid = tid >> 5;
    int px0 = (wid & 3) * 32, oc0 = (wid >> 2) * 64;

    const __nv_bfloat16* qh = g_qh + offb + ((size_t)(b * n + n0)) * d;
    const __nv_bfloat16* ql = g_ql + offb + ((size_t)(b * n + n0)) * d;
    const __nv_bfloat16* kh = g_kh + offb + ((size_t)(b * n + m0)) * d;
    const __nv_bfloat16* kl = g_kl + offb + ((size_t)(b * n + m0)) * d;

    FragC acc[2][4];
#pragma unroll
    for (int i = 0; i < 2; i++)
#pragma unroll
        for (int j = 0; j < 4; j++) wmma::fill_fragment(acc[i][j], 0.f);

    int k0s = z * dchunk;
    for (int k0 = k0s; k0 < k0s + dchunk; k0 += 128) {
        for (int idx = tid; idx < 2048; idx += 256) {
            int r = idx >> 4, k8 = (idx & 15) << 3;
            u32 dd = (u32)(r * 136 + k8) * 2;
            size_t go = (size_t)r * d + k0 + k8;
            cpa16(sb + QH + dd, qh + go);
            cpa16(sb + QL + dd, ql + go);
            cpa16(sb + KH + dd, kh + go);
            cpa16(sb + KL + dd, kl + go);
        }
        CP_COMMIT(); CP_WAIT(0);
        __syncthreads();
        mma3<false, FragB>((const __nv_bfloat16*)(smem + QH) + px0 * 136,
                           (const __nv_bfloat16*)(smem + QL) + px0 * 136,
                           (const __nv_bfloat16*)(smem + KH) + oc0 * 136,
                           (const __nv_bfloat16*)(smem + KL) + oc0 * 136, acc);
        __syncthreads();
    }

    size_t base = ((size_t)(z * NBm + b)) * n * n;
#pragma unroll
    for (int i = 0; i < 2; i++)
#pragma unroll
        for (int j = 0; j < 4; j++)
            wmma::store_matrix_sync(
                g_part + base + (size_t)(n0 + px0 + 16 * i) * n + m0 + oc0 + 16 * j,
                acc[i][j], n, wmma::mem_row_major);
}

// ============ reduce + softmax (+ optional bf16 attn output) ============
__global__ __launch_bounds__(256)
void softmax_kernel(int n, int nsplit, float isd, int wbf)
{
    __shared__ float sbuf[512];
    __shared__ float red[256];
    int row = blockIdx.x, b = blockIdx.y, tid = threadIdx.x;

    if (n <= 32) {
        int m = tid % n, zi = tid / n, tpm = 256 / n;
        float s = 0.f;
        for (int z = zi; z < nsplit; z += tpm)
            s += g_part[((size_t)(z * NBm + b) * n + row) * n + m];
        red[tid] = s;
        __syncthreads();
        if (tid < n) {
            float t = 0.f;
            for (int j = 0; j < tpm; j++) t += red[tid + j * n];
            sbuf[tid] = t * isd;
        }
    } else {
        for (int m = tid; m < n; m += 256) {
            float s = 0.f;
            for (int z = 0; z < nsplit; z++)
                s += g_part[((size_t)(z * NBm + b) * n + row) * n + m];
            sbuf[m] = s * isd;
        }
    }
    __syncthreads();

    float lm = -1e30f;
    for (int m = tid; m < n; m += 256) lm = fmaxf(lm, sbuf[m]);
    red[tid] = lm;
    __syncthreads();
    for (int s = 128; s > 0; s >>= 1) {
        if (tid < s) red[tid] = fmaxf(red[tid], red[tid + s]);
        __syncthreads();
    }
    float mx = red[0];
    __syncthreads();
    float ls = 0.f;
    for (int m = tid; m < n; m += 256) {
        float e = __expf(sbuf[m] - mx);
        sbuf[m] = e; ls += e;
    }
    red[tid] = ls;
    __syncthreads();
    for (int s = 128; s > 0; s >>= 1) {
        if (tid < s) red[tid] += red[tid + s];
        __syncthreads();
    }
    float inv = 1.0f / red[0];
    for (int m = tid; m < n; m += 256) {
        float p = sbuf[m] * inv;
        size_t o = ((size_t)b * n + row) * n + m;
        if (wbf) {
            __nv_bfloat16 h, l;
            bsplit(p, h, l);
            g_ath[o] = h; g_atl[o] = l;
        } else {
            g_attn[o] = p;
        }
    }
}

// ============ scalar AV (scales 0,1) ============
template<int BN, int TN>
__global__ __launch_bounds__(256)
void av2_kernel(int n, int d, long long off_ll)
{
    __shared__ float As[BN][34];
    __shared__ float Vs[32][66];
    size_t off = (size_t)off_ll;
    int b = blockIdx.z, n0 = blockIdx.y * BN, e0 = blockIdx.x * 64;
    int tx = threadIdx.x, ty = threadIdx.y, tid = ty * 16 + tx;

    ull acc[TN][2];
#pragma unroll
    for (int i = 0; i < TN; i++) { acc[i][0] = 0ull; acc[i][1] = 0ull; }
    int r0 = ty * TN;

    const float* vb = g_vw + off + e0;

    for (int m0 = 0; m0 < n; m0 += 32) {
        for (int idx = tid; idx < BN * 8; idx += 256) {
            int r = idx >> 3, c4 = (idx & 7) * 4;
            float4 v = (m0 + c4 < n)
                ? *(const float4*)(g_attn + ((size_t)(b * n + n0 + r)) * n + m0 + c4)
                : make_float4(0.f, 0.f, 0.f, 0.f);
            As[r][c4] = v.x; As[r][c4 + 1] = v.y; As[r][c4 + 2] = v.z; As[r][c4 + 3] = v.w;
        }
        for (int idx = tid; idx < 512; idx += 256) {
            int mm = idx >> 4, e4 = (idx & 15) * 4;
            float4 v = (m0 + mm < n)
                ? *(const float4*)(vb + ((size_t)(b * n + m0 + mm)) * d + e4)
                : make_float4(0.f, 0.f, 0.f, 0.f);
            Vs[mm][e4] = v.x; Vs[mm][e4 + 1] = v.y; Vs[mm][e4 + 2] = v.z; Vs[mm][e4 + 3] = v.w;
        }
        __syncthreads();
#pragma unroll
        for (int kk = 0; kk < 32; kk++) {
            ull v2a = *(const ull*)&Vs[kk][2 * tx];
            ull v2b = *(const ull*)&Vs[kk][2 * tx + 32];
#pragma unroll
            for (int i = 0; i < TN; i++) {
                ull a2 = pack2(As[r0 + i][kk]);
                ffma2(acc[i][0], a2, v2a);
                ffma2(acc[i][1], a2, v2b);
            }
        }
        __syncthreads();
    }

    float* ob = g_ow + off;
#pragma unroll
    for (int i = 0; i < TN; i++) {
        size_t rb = ((size_t)(b * n + n0 + r0 + i)) * d + e0;
        *(float2*)(ob + rb + 2 * tx)      = *reinterpret_cast<float2*>(&acc[i][0]);
        *(float2*)(ob + rb + 2 * tx + 32) = *reinterpret_cast<float2*>(&acc[i][1]);
    }
}

// ============ WMMA AV (scales 2,3) ============
__global__ __launch_bounds__(256)
void av_wmma_kernel(int n, int d, long long offb_ll, long long off32_ll)
{
    extern __shared__ __align__(16) char smem[];
    u32 sb = smem_u32(smem);
    const u32 AH = 0, AL = 34816, VH = 69632, VL = 104448;
    size_t offb = (size_t)offb_ll, off32 = (size_t)off32_ll;
    int b = blockIdx.z, n0 = blockIdx.y * 128, e0 = blockIdx.x * 128;
    int tid = threadIdx.x, wid = tid >> 5;
    int px0 = (wid & 3) * 32, oc0 = (wid >> 2) * 64;

    FragC acc[2][4];
#pragma unroll
    for (int i = 0; i < 2; i++)
#pragma unroll
        for (int j = 0; j < 4; j++) wmma::fill_fragment(acc[i][j], 0.f);

    for (int m0 = 0; m0 < n; m0 += 128) {
        for (int idx = tid; idx < 2048; idx += 256) {
            int r = idx >> 4, k8 = (idx & 15) << 3;
            u32 dd = (u32)(r * 136 + k8) * 2;
            size_t ao = ((size_t)(b * n + n0 + r)) * n + m0 + k8;
            size_t vo = offb + ((size_t)(b * n + m0 + r)) * d + e0 + k8;
            cpa16(sb + AH + dd, g_ath + ao);
            cpa16(sb + AL + dd, g_atl + ao);
            cpa16(sb + VH + dd, g_vh + vo);
            cpa16(sb + VL + dd, g_vl + vo);
        }
        CP_COMMIT(); CP_WAIT(0);
        __syncthreads();
        mma3<true, FragBr>((const __nv_bfloat16*)(smem + AH) + px0 * 136,
                           (const __nv_bfloat16*)(smem + AL) + px0 * 136,
                           (const __nv_bfloat16*)(smem + VH) + oc0,
                           (const __nv_bfloat16*)(smem + VL) + oc0, acc);
        __syncthreads();
    }

#pragma unroll
    for (int i = 0; i < 2; i++)
#pragma unroll
        for (int j = 0; j < 4; j++)
            wmma::store_matrix_sync(
                g_ow + off32 + ((size_t)(b * n + n0 + px0 + 16 * i)) * d + e0 + oc0 + 16 * j,
                acc[i][j], d, wmma::mem_row_major);
}

// ============ unpack windowed -> channel-last bf16 hi/lo ============
__global__ __launch_bounds__(256)
void unpack2_kernel()
{
    __shared__ float sbm[64][130];
    int y = blockIdx.x, img = blockIdx.y, tid = threadIdx.x;
    int b = img >> 3, t = img & 7;
    for (int ch = 0; ch < 2; ch++) {
        for (int idx = tid; idx < 64 * 128; idx += 256) {
            int cl = idx >> 7, xp = idx & 127;
            int c = ch * 64 + cl;
            int s = c >> 5, lph = 7 - s;
            int phm = (1 << lph) - 1;
            int n_s = 8 << (2 * s), d_s = 524288 >> (2 * s);
            int oy = y >> lph, py = y & phm;
            int ox = xp >> lph, pxm = xp & phm;
            int tok = ((((t << s) + oy) << s) + ox);
            int e = ((((c & 31) << lph) + py) << lph) + pxm;
            sbm[cl][xp] = g_ow[(size_t)s * 8388608 + ((size_t)(b * n_s + tok)) * d_s + e];
        }
        __syncthreads();
        for (int idx = tid; idx < 64 * 128; idx += 256) {
            int px = idx >> 6, cl = idx & 63;
            __nv_bfloat16 h, l;
            bsplit(sbm[cl][px], h, l);
            size_t o = (((size_t)img * 128 + y) * 128 + px) * 128 + ch * 64 + cl;
            g_ah[o] = h; g_al[o] = l;
        }
        __syncthreads();
    }
}

// ============ conv3x3: N=64 split, 2 CTAs/SM, persistent acc ============
// blockIdx.x = y*2 + oh. block 128. smem 107584.
__global__ __launch_bounds__(128, 2)
void conv3_v3_kernel(const float* __restrict__ bias, float* __restrict__ out)
{
    extern __shared__ __align__(16) char smem[];
    u32 sb = smem_u32(smem);
    const u32 AH = 0, AL = 35360, BH = 70720, BL = 88128;

    int bx = blockIdx.x, img = blockIdx.y;
    int y = bx >> 1, oh = bx & 1;
    int tid = threadIdx.x, wid = tid >> 5;
    int px0 = wid * 32;

    FragC acc[2][4];
#pragma unroll
    for (int i = 0; i < 2; i++)
#pragma unroll
        for (int j = 0; j < 4; j++) wmma::fill_fragment(acc[i][j], 0.f);

    for (int tp = 0; tp < 9; tp++) {
        int ky = tp / 3, kx = tp - ky * 3;
        __syncthreads();     // prior MMA done before overwriting A/B
        if (kx == 0) {
            int yy = y + ky - 1;
            bool yok = (yy >= 0 && yy < 128);
            size_t abase = (((size_t)img * 128 + (yok ? yy : 0)) * 128) * 128;
            for (int idx = tid; idx < 2080; idx += 128) {
                int i = idx >> 4, k8 = (idx & 15) << 3;
                int px = i - 1;
                u32 d = (u32)(i * 136 + k8) * 2;
                if (yok && px >= 0 && px < 128) {
                    size_t o = abase + (size_t)px * 128 + k8;
                    cpa16(sb + AH + d, g_ah + o);
                    cpa16(sb + AL + d, g_al + o);
                } else {
                    uint4 zz = make_uint4(0, 0, 0, 0);
                    *(uint4*)(smem + AH + d) = zz;
                    *(uint4*)(smem + AL + d) = zz;
                }
            }
        }
        const __nv_bfloat16* wh = g_w3h + (size_t)tp * 16384 + oh * 8192;
        const __nv_bfloat16* wl = g_w3l + (size_t)tp * 16384 + oh * 8192;
        for (int idx = tid; idx < 1024; idx += 128) {
            int row = idx >> 4, k8 = (idx & 15) << 3;
            u32 d = (u32)(row * 136 + k8) * 2;
            cpa16(sb + BH + d, wh + row * 128 + k8);
            cpa16(sb + BL + d, wl + row * 128 + k8);
        }
        CP_COMMIT(); CP_WAIT(0);
        __syncthreads();

        mma3<false, FragB>((const __nv_bfloat16*)(smem + AH) + (px0 + kx) * 136,
                           (const __nv_bfloat16*)(smem + AL) + (px0 + kx) * 136,
                           (const __nv_bfloat16*)(smem + BH),
                           (const __nv_bfloat16*)(smem + BL), acc);
    }
    __syncthreads();

    float* Cs = (float*)(smem + BH);    // [128][72] — ldm multiple of 4 floats
#pragma unroll
    for (int i = 0; i < 2; i++)
#pragma unroll
        for (int j = 0; j < 4; j++)
            wmma::store_matrix_sync(&Cs[(px0 + 16 * i) * 72 + 16 * j],
                                    acc[i][j], 72, wmma::mem_row_major);
    __syncthreads();

    for (int idx = tid; idx < 8192; idx += 128) {
        int oc = idx >> 7, px = idx & 127;
        float v = Cs[px * 72 + oc] + bias[oh * 64 + oc];
        out[((size_t)img * 128 + oh * 64 + oc) * HWs + (size_t)y * 128 + px] =
            fmaxf(v, 0.f);
    }
}

// ============ launch ============
extern "C" void kernel_launch(void* const* d_in, const int* in_sizes, int n_in,
                              void* d_out, int out_size)
{
    const float* x  = (const float*)d_in[0];
    const float* wq = (const float*)d_in[1];
    const float* bq = (const float*)d_in[2];
    const float* wk = (const float*)d_in[3];
    const float* bk = (const float*)d_in[4];
    const float* wv = (const float*)d_in[5];
    const float* bv = (const float*)d_in[6];
    const float* wo = (const float*)d_in[7];
    const float* bo = (const float*)d_in[8];
    float* out = (float*)d_out;

    const int smem1 = 104448, smem3 = 107584, smemW = 139264, smemS = 67584;
    cudaFuncSetAttribute(conv1_v3_kernel,
                         cudaFuncAttributeMaxDynamicSharedMemorySize, smem1);
    cudaFuncSetAttribute(conv3_v3_kernel,
                         cudaFuncAttributeMaxDynamicSharedMemorySize, smem3);
    cudaFuncSetAttribute(scores_wmma_kernel,
                         cudaFuncAttributeMaxDynamicSharedMemorySize, smemW);
    cudaFuncSetAttribute(av_wmma_kernel,
                         cudaFuncAttributeMaxDynamicSharedMemorySize, smemW);
    cudaFuncSetAttribute(qkv_scatter_kernel,
                         cudaFuncAttributeMaxDynamicSharedMemorySize, smemS);

    dim3 blk(16, 16);

    prep_w3_kernel<<<(9 * 128 * 128 + 255) / 256, 256>>>(wo);
    prep_w1_kernel<<<(3 * 16384 + 255) / 256, 256>>>(wq, wk, wv);
    prep_x_kernel<<<dim3(Hd, BT), 256>>>(x);
    conv1_v3_kernel<<<dim3(768, BT), 128, smem1>>>();
    qkv_scatter_kernel<<<dim3(Hd, BT), 256, smemS>>>(bq, bk, bv);

    // scale 0: n=8, d=524288 (scalar fp32)
    {
        float isd = 1.0f / sqrtf(524288.f);
        scores0_kernel<<<dim3(1024, NBm), 256>>>();
        softmax_kernel<<<dim3(8, NBm), 256>>>(8, 1024, isd, 0);
        av2_kernel<8, 1><<<dim3(524288 / 64, 1, NBm), blk>>>(8, 524288, 0LL);
    }
    // scale 1: n=32, d=131072 (scalar fp32)
    {
        float isd = 1.0f / sqrtf(131072.f);
        scores2_kernel<32, 2><<<dim3(1, NBm, 256), blk>>>(32, 131072, 8388608LL, 1, 512);
        softmax_kernel<<<dim3(32, NBm), 256>>>(32, 256, isd, 0);
        av2_kernel<32, 2><<<dim3(131072 / 64, 1, NBm), blk>>>(32, 131072, 8388608LL);
    }
    // scale 2: n=128, d=32768 (WMMA)
    {
        float isd = 1.0f / sqrtf(32768.f);
        scores_wmma_kernel<<<dim3(1, NBm, 128), 256, smemW>>>(128, 32768, 0LL, 1, 256);
        softmax_kernel<<<dim3(128, NBm), 256>>>(128, 128, isd, 1);
        av_wmma_kernel<<<dim3(256, 1, NBm), 256, smemW>>>(128, 32768, 0LL, 2LL * 8388608);
    }
    // scale 3: n=512, d=8192 (WMMA)
    {
        float isd = 1.0f / sqrtf(8192.f);
        scores_wmma_kernel<<<dim3(16, NBm, 8), 256, smemW>>>(512, 8192, 8388608LL, 4, 1024);
        softmax_kernel<<<dim3(512, NBm), 256>>>(512, 8, isd, 1);
        av_wmma_kernel<<<dim3(64, 4, NBm), 256, smemW>>>(512, 8192, 8388608LL, 3LL * 8388608);
    }

    unpack2_kernel<<<dim3(Hd, BT), 256>>>();
    conv3_v3_kernel<<<dim3(256, BT), 128, smem3>>>(bo, out);

    (void)in_sizes; (void)n_in; (void)out_size;
}